// round 12
// baseline (speedup 1.0000x reference)
#include <cuda_runtime.h>
#include <cuda_fp16.h>
#include <math.h>
#include <stdint.h>

#define E_NUM  131072
#define NN     32768
#define DM     256
#define HIDN   512
#define MSGD   256

// ---------------- scratch (static device globals; no allocation) ----------
__device__ __half g_hh [(size_t)E_NUM * HIDN];   // 134 MB (h, fp16)
__device__ float g_tenc[(size_t)E_NUM * 64];     // 33.5 MB
__device__ float g_sums[(size_t)NN * MSGD];      // 33.5 MB (indexed by id)
__device__ float g_agg [(size_t)NN * MSGD];      // 33.5 MB (unique-slot order)
__device__ float g_gih [(size_t)NN * 3 * DM];    // 100 MB
__device__ float g_ghh [(size_t)NN * 3 * DM];    // 100 MB
__device__ int   g_cnt [NN];
__device__ int   g_uid [NN];
__device__ int   g_is64;

// ---------------- helpers ---------------------------------------------------
__device__ __forceinline__ uint32_t smem_u32(const void* p) {
    uint32_t a;
    asm("{ .reg .u64 t; cvta.to.shared.u64 t, %1; cvt.u32.u64 %0, t; }"
        : "=r"(a) : "l"(p));
    return a;
}
__device__ __forceinline__ void mma16(float* d, const uint32_t* a, const uint32_t* b) {
    asm volatile("mma.sync.aligned.m16n8k16.row.col.f32.f16.f16.f32 "
                 "{%0,%1,%2,%3}, {%4,%5,%6,%7}, {%8,%9}, {%0,%1,%2,%3};"
                 : "+f"(d[0]), "+f"(d[1]), "+f"(d[2]), "+f"(d[3])
                 : "r"(a[0]), "r"(a[1]), "r"(a[2]), "r"(a[3]),
                   "r"(b[0]), "r"(b[1]));
}
__device__ __forceinline__ void ldsm4(uint32_t* r, uint32_t addr) {
    asm volatile("ldmatrix.sync.aligned.m8n8.x4.shared.b16 {%0,%1,%2,%3}, [%4];"
                 : "=r"(r[0]), "=r"(r[1]), "=r"(r[2]), "=r"(r[3]) : "r"(addr));
}
__device__ __forceinline__ void ldsm2(uint32_t* r, uint32_t addr) {
    asm volatile("ldmatrix.sync.aligned.m8n8.x2.shared.b16 {%0,%1}, [%2];"
                 : "=r"(r[0]), "=r"(r[1]) : "r"(addr));
}

// ---------------- dtype detector for dst_ids (int32 vs int64) -------------
__global__ void k_detect(const int* ids32) {
    if (threadIdx.x == 0 && blockIdx.x == 0) {
        int z = 0;
        for (int i = 1; i < 64; i += 2) z |= ids32[i];
        g_is64 = (z == 0) ? 1 : 0;
    }
}
__device__ __forceinline__ int load_id(const void* idsv, int e) {
    if (g_is64) return (int)((const long long*)idsv)[e];
    return ((const int*)idsv)[e];
}

// ---------------- per-launch init ------------------------------------------
__global__ void k_zero(float* out, int write_ids) {
    int idx = blockIdx.x * blockDim.x + threadIdx.x;  // NN*MSGD threads
    g_sums[idx] = 0.0f;
    if (idx < NN) {
        g_cnt[idx] = 0;
        g_uid[idx] = NN;
        if (write_ids) out[idx] = (float)NN;
    }
}

// ---------------- time encoding --------------------------------------------
__global__ void k_tenc(const float* __restrict__ rt, const float* __restrict__ tw,
                       const float* __restrict__ tb) {
    int idx = blockIdx.x * blockDim.x + threadIdx.x;  // E*64
    int e = idx >> 6, j = idx & 63;
    g_tenc[idx] = cosf(fmaf(rt[e], tw[j], tb[j]));
}

// ---------------- per-id counts --------------------------------------------
__global__ void k_count(const void* idsv) {
    int e = blockIdx.x * blockDim.x + threadIdx.x;
    if (e < E_NUM) atomicAdd(&g_cnt[load_id(idsv, e)], 1);
}

// ---------------- sorted-unique (ballot-based, coalesced) -------------------
__global__ void k_scan(float* out, int write_ids) {
    __shared__ uint32_t masks[32][32];
    __shared__ int wtot[32];
    int lane = threadIdx.x & 31, wid = threadIdx.x >> 5;
    int tot = 0;
#pragma unroll
    for (int i = 0; i < 32; i++) {
        int id = wid * 1024 + i * 32 + lane;
        uint32_t m = __ballot_sync(0xFFFFFFFFu, g_cnt[id] > 0);
        masks[wid][i] = m;
        tot += __popc(m);
    }
    if (lane == 0) wtot[wid] = tot;
    __syncthreads();
    if (wid == 0) {
        int w = wtot[lane], v = w;
#pragma unroll
        for (int off = 1; off < 32; off <<= 1) {
            int t = __shfl_up_sync(0xFFFFFFFFu, v, off);
            if (lane >= off) v += t;
        }
        wtot[lane] = v - w;   // exclusive
    }
    __syncthreads();
    int r = wtot[wid];
#pragma unroll
    for (int i = 0; i < 32; i++) {
        uint32_t m = masks[wid][i];
        int id = wid * 1024 + i * 32 + lane;
        if (m & (1u << lane)) {
            int rk = r + __popc(m & ((1u << lane) - 1u));
            g_uid[rk] = id;
            if (write_ids) out[rk] = (float)id;
        }
        r += __popc(m);
    }
}

// ---------------- agg = sums/count in unique-slot order ---------------------
__global__ void k_agg() {
    int idx = blockIdx.x * blockDim.x + threadIdx.x;  // NN*64
    int u = idx >> 6;
    int c4 = (idx & 63) << 2;
    int id = g_uid[u];
    float4 o = make_float4(0.f, 0.f, 0.f, 0.f);
    if (id < NN) {
        float cnt = (float)g_cnt[id];
        float4 s = *reinterpret_cast<const float4*>(g_sums + (size_t)id * MSGD + c4);
        o.x = s.x / cnt; o.y = s.y / cnt; o.z = s.z / cnt; o.w = s.w / cnt;
    }
    *reinterpret_cast<float4*>(g_agg + (size_t)u * MSGD + c4) = o;
}

// ---------------- fp16 mma.sync GEMM: C = A(MxK) * B(NxK)^T + bias ----------
// CTA 128x128, 8 warps (2x4), warp tile 64x32 of m16n8k16 frags, KCH=16.
// Smem rows: 40 halves (80B stride) -> conflict-free ldmatrix.
// AMODE: 0 = f32 A, 1 = half A, 2 = concat f32 sources.
// OMODE: 0 = f32 store, 1 = half store (+relu), 2 = scatter-atomic into g_sums.
#define KCH   16
#define ROWH  40
#define TILE_HALFS (128 * ROWH)                  // 5120 halves
#define STAGE_HALFS (2 * TILE_HALFS)             // A + B
#define SMEM_HALFS  (2 * STAGE_HALFS)            // 2 stages = 40960 B

template <int AMODE, int OMODE>
__global__ void __launch_bounds__(256, 2)
mma_gemm(const void* __restrict__ Av, const float* __restrict__ Bw,
         const float* __restrict__ bias, void* __restrict__ Cv,
         int K, int Nld, int relu, const void* __restrict__ idsv,
         const float* __restrict__ s0, const float* __restrict__ s1,
         const float* __restrict__ s2, const float* __restrict__ s3)
{
    __shared__ __half sm[SMEM_HALFS];
    const int tid  = threadIdx.x;
    const int lane = tid & 31;
    const int wid  = tid >> 5;
    const int wm   = wid >> 2;      // 0..1  (64-row slabs)
    const int wn   = wid & 3;       // 0..3  (32-col slabs)
    const int rowBase = blockIdx.y * 128;
    const int colBase = blockIdx.x * 128;
    const uint32_t sb = smem_u32(sm);

    float acc[4][4][4];
#pragma unroll
    for (int mt = 0; mt < 4; mt++)
#pragma unroll
        for (int nt = 0; nt < 4; nt++)
#pragma unroll
            for (int r = 0; r < 4; r++) acc[mt][nt][r] = 0.0f;

    const int Cn = K / KCH;
    const int arow = tid >> 2, aseg = tid & 3;            // i=0 plane
    const int brow = (tid + 256) >> 2;                    // wait: B uses same pattern

    // prefetch buffers (ping-pong)
    float4 afb[2][2], bfb[2][2];
    uint2  ahb[2][2];

    // ---- loader: fetch chunk c into buffer set s
    auto fetch = [&](int c, int s) {
        int k0 = c * KCH;
        const float* bs = Bw + (size_t)colBase * K + k0;
#pragma unroll
        for (int i = 0; i < 2; ++i) {
            int idx = tid + (i << 8);
            int row = idx >> 2, seg = idx & 3;
            bfb[s][i] = *reinterpret_cast<const float4*>(bs + (size_t)row * K + seg * 4);
        }
        if (AMODE == 1) {
            const __half* ah = (const __half*)Av + (size_t)rowBase * K + k0;
#pragma unroll
            for (int i = 0; i < 2; ++i) {
                int idx = tid + (i << 8);
                int row = idx >> 2, seg = idx & 3;
                ahb[s][i] = *reinterpret_cast<const uint2*>(ah + (size_t)row * K + seg * 4);
            }
        } else {
            const float* as; int ast;
            if (AMODE == 2) {
                if (k0 < 256)      { as = s0 + (size_t)rowBase * 256 + k0;         ast = 256; }
                else if (k0 < 512) { as = s1 + (size_t)rowBase * 256 + (k0 - 256); ast = 256; }
                else if (k0 < 640) { as = s2 + (size_t)rowBase * 128 + (k0 - 512); ast = 128; }
                else               { as = s3 + (size_t)rowBase * 64  + (k0 - 640); ast = 64;  }
            } else {
                as = (const float*)Av + (size_t)rowBase * K + k0; ast = K;
            }
#pragma unroll
            for (int i = 0; i < 2; ++i) {
                int idx = tid + (i << 8);
                int row = idx >> 2, seg = idx & 3;
                afb[s][i] = *reinterpret_cast<const float4*>(as + (size_t)row * ast + seg * 4);
            }
        }
    };
    // ---- store buffer set s into smem stage st
    auto stsbuf = [&](int s, int st) {
        __half* Ab = sm + st * STAGE_HALFS;
        __half* Bb = Ab + TILE_HALFS;
#pragma unroll
        for (int i = 0; i < 2; ++i) {
            int idx = tid + (i << 8);
            int row = idx >> 2, seg = idx & 3;
            uint2 u;
            if (AMODE == 1) {
                u = ahb[s][i];
            } else {
                __half2 h0 = __floats2half2_rn(afb[s][i].x, afb[s][i].y);
                __half2 h1 = __floats2half2_rn(afb[s][i].z, afb[s][i].w);
                u.x = *(uint32_t*)&h0; u.y = *(uint32_t*)&h1;
            }
            *reinterpret_cast<uint2*>(Ab + row * ROWH + seg * 4) = u;
            __half2 g0 = __floats2half2_rn(bfb[s][i].x, bfb[s][i].y);
            __half2 g1 = __floats2half2_rn(bfb[s][i].z, bfb[s][i].w);
            uint2 v; v.x = *(uint32_t*)&g0; v.y = *(uint32_t*)&g1;
            *reinterpret_cast<uint2*>(Bb + row * ROWH + seg * 4) = v;
        }
    };

    fetch(0, 0);
    for (int c = 0; c < Cn; ++c) {
        stsbuf(c & 1, c & 1);
        __syncthreads();
        if (c + 1 < Cn) fetch(c + 1, (c + 1) & 1);

        const uint32_t Ab = sb + (uint32_t)(c & 1) * STAGE_HALFS * 2;
        const uint32_t Bb = Ab + TILE_HALFS * 2;

        uint32_t af[4][4], bf[4][2];
        // A frags: x4 per m16 tile. lane -> matrix l>>3, row l&7.
        // m0: rows r0..+7 k0 ; m1: rows r0+8..+15 k0 ; m2: r0.. k8 ; m3: r0+8.. k8
        {
            int arw = (lane & 7) + ((lane >> 3) & 1) * 8;
            int acl = (lane >> 4) * 8;
#pragma unroll
            for (int mt = 0; mt < 4; mt++) {
                int r0 = wm * 64 + mt * 16;
                ldsm4(af[mt], Ab + (uint32_t)((r0 + arw) * ROWH + acl) * 2);
            }
        }
        // B frags: x2 per n8 tile. lanes 0-7 -> rows n0..+7 col0; 8-15 -> col8.
        {
            int l = lane & 15;
            int brw = l & 7;
            int bcl = (l >> 3) * 8;
#pragma unroll
            for (int nt = 0; nt < 4; nt++) {
                int n0 = wn * 32 + nt * 8;
                ldsm2(bf[nt], Bb + (uint32_t)((n0 + brw) * ROWH + bcl) * 2);
            }
        }
#pragma unroll
        for (int mt = 0; mt < 4; mt++)
#pragma unroll
            for (int nt = 0; nt < 4; nt++)
                mma16(acc[mt][nt], af[mt], bf[nt]);
        __syncthreads();
    }

    // ---- epilogue
#pragma unroll
    for (int mt = 0; mt < 4; mt++) {
        int r0 = rowBase + wm * 64 + mt * 16 + (lane >> 2);
        int id0 = 0, id1 = 0;
        if (OMODE == 2) { id0 = load_id(idsv, r0); id1 = load_id(idsv, r0 + 8); }
#pragma unroll
        for (int nt = 0; nt < 4; nt++) {
            int c0 = colBase + wn * 32 + nt * 8 + (lane & 3) * 2;
            float bv0 = bias[c0], bv1 = bias[c0 + 1];
            float o00 = acc[mt][nt][0] + bv0, o01 = acc[mt][nt][1] + bv1;
            float o10 = acc[mt][nt][2] + bv0, o11 = acc[mt][nt][3] + bv1;
            if (relu) {
                o00 = fmaxf(o00, 0.f); o01 = fmaxf(o01, 0.f);
                o10 = fmaxf(o10, 0.f); o11 = fmaxf(o11, 0.f);
            }
            if (OMODE == 0) {
                float* Co = (float*)Cv;
                *reinterpret_cast<float2*>(Co + (size_t)r0 * Nld + c0) = make_float2(o00, o01);
                *reinterpret_cast<float2*>(Co + (size_t)(r0 + 8) * Nld + c0) = make_float2(o10, o11);
            } else if (OMODE == 1) {
                __half* Ch = (__half*)Cv;
                *reinterpret_cast<__half2*>(Ch + (size_t)r0 * Nld + c0) = __floats2half2_rn(o00, o01);
                *reinterpret_cast<__half2*>(Ch + (size_t)(r0 + 8) * Nld + c0) = __floats2half2_rn(o10, o11);
            } else {
                atomicAdd(&g_sums[(size_t)id0 * MSGD + c0],     o00);
                atomicAdd(&g_sums[(size_t)id0 * MSGD + c0 + 1], o01);
                atomicAdd(&g_sums[(size_t)id1 * MSGD + c0],     o10);
                atomicAdd(&g_sums[(size_t)id1 * MSGD + c0 + 1], o11);
            }
        }
    }
}

// ---------------- GRU gates + output ----------------------------------------
__global__ void k_gate(const float* __restrict__ dstm, float* __restrict__ out,
                       int mem_off) {
    int idx = blockIdx.x * blockDim.x + threadIdx.x;  // NN*DM
    int u = idx >> 8;
    int c = idx & 255;
    const float* gi = g_gih + (size_t)u * (3 * DM);
    const float* gh = g_ghh + (size_t)u * (3 * DM);
    float r = 1.0f / (1.0f + expf(-(gi[c] + gh[c])));
    float z = 1.0f / (1.0f + expf(-(gi[256 + c] + gh[256 + c])));
    float n = tanhf(gi[512 + c] + r * gh[512 + c]);
    float prev = dstm[idx];
    out[mem_off + idx] = (1.0f - z) * n + z * prev;
}

// ---------------- launch -----------------------------------------------------
extern "C" void kernel_launch(void* const* d_in, const int* in_sizes, int n_in,
                              void* d_out, int out_size)
{
    const float* rel_time = (const float*)d_in[0];
    const float* srcm     = (const float*)d_in[1];
    const float* dstm     = (const float*)d_in[2];
    const float* edgef    = (const float*)d_in[3];
    const void*  idsv     =               d_in[4];
    const float* tw       = (const float*)d_in[5];
    const float* tb       = (const float*)d_in[6];
    const float* w1       = (const float*)d_in[7];
    const float* b1       = (const float*)d_in[8];
    const float* w2       = (const float*)d_in[9];
    const float* b2       = (const float*)d_in[10];
    const float* wih      = (const float*)d_in[11];
    const float* whh      = (const float*)d_in[12];
    const float* bih      = (const float*)d_in[13];
    const float* bhh      = (const float*)d_in[14];
    float* out = (float*)d_out;

    int write_ids = (out_size >= NN + NN * DM) ? 1 : 0;
    int mem_off   = write_ids ? NN : 0;

    void *p_hh; float *p_agg, *p_gih, *p_ghh, *p_tenc;
    cudaGetSymbolAddress(&p_hh, g_hh);
    cudaGetSymbolAddress((void**)&p_agg,  g_agg);
    cudaGetSymbolAddress((void**)&p_gih,  g_gih);
    cudaGetSymbolAddress((void**)&p_ghh,  g_ghh);
    cudaGetSymbolAddress((void**)&p_tenc, g_tenc);

    k_detect<<<1, 32>>>((const int*)idsv);
    k_zero<<<(NN * MSGD) / 256, 256>>>(out, write_ids);
    k_count<<<E_NUM / 256, 256>>>(idsv);
    k_scan<<<1, 1024>>>(out, write_ids);
    k_tenc<<<(E_NUM * 64) / 256, 256>>>(rel_time, tw, tb);

    // GEMM1: h = relu([src|dst|edge|t_enc] @ w1^T + b1) -> fp16   131072x512, K=704
    mma_gemm<2, 1><<<dim3(HIDN / 128, E_NUM / 128), 256>>>(
        nullptr, w1, b1, p_hh, 704, HIDN, 1, nullptr, srcm, dstm, edgef, p_tenc);

    // GEMM2: msg = h @ w2^T + b2, scatter-atomic into g_sums     131072x256, K=512
    mma_gemm<1, 2><<<dim3(MSGD / 128, E_NUM / 128), 256>>>(
        p_hh, w2, b2, nullptr, 512, MSGD, 0, idsv, nullptr, nullptr, nullptr, nullptr);

    k_agg<<<(NN * 64) / 256, 256>>>();

    // GRU: gi = agg @ wih^T + bih ; gh = prev @ whh^T + bhh       32768x768, K=256
    mma_gemm<0, 0><<<dim3((3 * DM) / 128, NN / 128), 256>>>(
        p_agg, wih, bih, p_gih, 256, 3 * DM, 0, nullptr, nullptr, nullptr, nullptr, nullptr);
    mma_gemm<0, 0><<<dim3((3 * DM) / 128, NN / 128), 256>>>(
        dstm, whh, bhh, p_ghh, 256, 3 * DM, 0, nullptr, nullptr, nullptr, nullptr, nullptr);

    k_gate<<<(NN * DM) / 256, 256>>>(dstm, out, mem_off);
}

// round 13
// speedup vs baseline: 1.0014x; 1.0014x over previous
#include <cuda_runtime.h>
#include <cuda_fp16.h>
#include <math.h>
#include <stdint.h>

#define E_NUM  131072
#define NN     32768
#define DM     256
#define HIDN   512
#define MSGD   256

// ---------------- scratch (static device globals; no allocation) ----------
__device__ __half g_hh [(size_t)E_NUM * HIDN];   // 134 MB (h, fp16)
__device__ float g_tenc[(size_t)E_NUM * 64];     // 33.5 MB
__device__ float g_sums[(size_t)NN * MSGD];      // 33.5 MB (indexed by id)
__device__ float g_agg [(size_t)NN * MSGD];      // 33.5 MB (unique-slot order)
__device__ float g_gih [(size_t)NN * 3 * DM];    // 100 MB
__device__ float g_ghh [(size_t)NN * 3 * DM];    // 100 MB
__device__ int   g_cnt [NN];
__device__ int   g_uid [NN];
__device__ int   g_is64;

// ---------------- helpers ---------------------------------------------------
__device__ __forceinline__ uint32_t smem_u32(const void* p) {
    uint32_t a;
    asm("{ .reg .u64 t; cvta.to.shared.u64 t, %1; cvt.u32.u64 %0, t; }"
        : "=r"(a) : "l"(p));
    return a;
}
__device__ __forceinline__ void mma16(float* d, const uint32_t* a, const uint32_t* b) {
    asm volatile("mma.sync.aligned.m16n8k16.row.col.f32.f16.f16.f32 "
                 "{%0,%1,%2,%3}, {%4,%5,%6,%7}, {%8,%9}, {%0,%1,%2,%3};"
                 : "+f"(d[0]), "+f"(d[1]), "+f"(d[2]), "+f"(d[3])
                 : "r"(a[0]), "r"(a[1]), "r"(a[2]), "r"(a[3]),
                   "r"(b[0]), "r"(b[1]));
}
__device__ __forceinline__ void ldsm4(uint32_t* r, uint32_t addr) {
    asm volatile("ldmatrix.sync.aligned.m8n8.x4.shared.b16 {%0,%1,%2,%3}, [%4];"
                 : "=r"(r[0]), "=r"(r[1]), "=r"(r[2]), "=r"(r[3]) : "r"(addr));
}
__device__ __forceinline__ void ldsm2(uint32_t* r, uint32_t addr) {
    asm volatile("ldmatrix.sync.aligned.m8n8.x2.shared.b16 {%0,%1}, [%2];"
                 : "=r"(r[0]), "=r"(r[1]) : "r"(addr));
}

// ---------------- dtype detector for dst_ids (int32 vs int64) -------------
__global__ void k_detect(const int* ids32) {
    if (threadIdx.x == 0 && blockIdx.x == 0) {
        int z = 0;
        for (int i = 1; i < 64; i += 2) z |= ids32[i];
        g_is64 = (z == 0) ? 1 : 0;
    }
}
__device__ __forceinline__ int load_id(const void* idsv, int e) {
    if (g_is64) return (int)((const long long*)idsv)[e];
    return ((const int*)idsv)[e];
}

// ---------------- per-launch init ------------------------------------------
__global__ void k_zero(float* out, int write_ids) {
    int idx = blockIdx.x * blockDim.x + threadIdx.x;  // NN*MSGD threads
    g_sums[idx] = 0.0f;
    if (idx < NN) {
        g_cnt[idx] = 0;
        g_uid[idx] = NN;
        if (write_ids) out[idx] = (float)NN;
    }
}

// ---------------- time encoding --------------------------------------------
__global__ void k_tenc(const float* __restrict__ rt, const float* __restrict__ tw,
                       const float* __restrict__ tb) {
    int idx = blockIdx.x * blockDim.x + threadIdx.x;  // E*64
    int e = idx >> 6, j = idx & 63;
    g_tenc[idx] = cosf(fmaf(rt[e], tw[j], tb[j]));
}

// ---------------- per-id counts --------------------------------------------
__global__ void k_count(const void* idsv) {
    int e = blockIdx.x * blockDim.x + threadIdx.x;
    if (e < E_NUM) atomicAdd(&g_cnt[load_id(idsv, e)], 1);
}

// ---------------- sorted-unique (ballot-based, coalesced) -------------------
__global__ void k_scan(float* out, int write_ids) {
    __shared__ uint32_t masks[32][32];
    __shared__ int wtot[32];
    int lane = threadIdx.x & 31, wid = threadIdx.x >> 5;
    int tot = 0;
#pragma unroll
    for (int i = 0; i < 32; i++) {
        int id = wid * 1024 + i * 32 + lane;
        uint32_t m = __ballot_sync(0xFFFFFFFFu, g_cnt[id] > 0);
        masks[wid][i] = m;
        tot += __popc(m);
    }
    if (lane == 0) wtot[wid] = tot;
    __syncthreads();
    if (wid == 0) {
        int w = wtot[lane], v = w;
#pragma unroll
        for (int off = 1; off < 32; off <<= 1) {
            int t = __shfl_up_sync(0xFFFFFFFFu, v, off);
            if (lane >= off) v += t;
        }
        wtot[lane] = v - w;   // exclusive
    }
    __syncthreads();
    int r = wtot[wid];
#pragma unroll
    for (int i = 0; i < 32; i++) {
        uint32_t m = masks[wid][i];
        int id = wid * 1024 + i * 32 + lane;
        if (m & (1u << lane)) {
            int rk = r + __popc(m & ((1u << lane) - 1u));
            g_uid[rk] = id;
            if (write_ids) out[rk] = (float)id;
        }
        r += __popc(m);
    }
}

// ---------------- agg = sums/count in unique-slot order ---------------------
__global__ void k_agg() {
    int idx = blockIdx.x * blockDim.x + threadIdx.x;  // NN*64
    int u = idx >> 6;
    int c4 = (idx & 63) << 2;
    int id = g_uid[u];
    float4 o = make_float4(0.f, 0.f, 0.f, 0.f);
    if (id < NN) {
        float cnt = (float)g_cnt[id];
        float4 s = *reinterpret_cast<const float4*>(g_sums + (size_t)id * MSGD + c4);
        o.x = s.x / cnt; o.y = s.y / cnt; o.z = s.z / cnt; o.w = s.w / cnt;
    }
    *reinterpret_cast<float4*>(g_agg + (size_t)u * MSGD + c4) = o;
}

// ---------------- fp16 mma.sync GEMM: C = A(MxK) * B(NxK)^T + bias ----------
// CTA 128x128, 8 warps (2x4), warp tile 64x32 of m16n8k16 frags, KCH=16.
// Smem rows: 40 halves (80B stride) -> conflict-free ldmatrix.
// AMODE: 0 = f32 A, 1 = half A, 2 = concat f32 sources.
// OMODE: 0 = f32 store, 1 = half store (+relu), 2 = scatter-atomic into g_sums.
#define KCH   16
#define ROWH  40
#define TILE_HALFS (128 * ROWH)                  // 5120 halves
#define STAGE_HALFS (2 * TILE_HALFS)             // A + B
#define SMEM_HALFS  (2 * STAGE_HALFS)            // 2 stages = 40960 B

template <int AMODE, int OMODE>
__global__ void __launch_bounds__(256, 2)
mma_gemm(const void* __restrict__ Av, const float* __restrict__ Bw,
         const float* __restrict__ bias, void* __restrict__ Cv,
         int K, int Nld, int relu, const void* __restrict__ idsv,
         const float* __restrict__ s0, const float* __restrict__ s1,
         const float* __restrict__ s2, const float* __restrict__ s3)
{
    __shared__ __half sm[SMEM_HALFS];
    const int tid  = threadIdx.x;
    const int lane = tid & 31;
    const int wid  = tid >> 5;
    const int wm   = wid >> 2;      // 0..1  (64-row slabs)
    const int wn   = wid & 3;       // 0..3  (32-col slabs)
    const int rowBase = blockIdx.y * 128;
    const int colBase = blockIdx.x * 128;
    const uint32_t sb = smem_u32(sm);

    float acc[4][4][4];
#pragma unroll
    for (int mt = 0; mt < 4; mt++)
#pragma unroll
        for (int nt = 0; nt < 4; nt++)
#pragma unroll
            for (int r = 0; r < 4; r++) acc[mt][nt][r] = 0.0f;

    const int Cn = K / KCH;
    const int arow = tid >> 2, aseg = tid & 3;            // i=0 plane
    const int brow = (tid + 256) >> 2;                    // wait: B uses same pattern

    // prefetch buffers (ping-pong)
    float4 afb[2][2], bfb[2][2];
    uint2  ahb[2][2];

    // ---- loader: fetch chunk c into buffer set s
    auto fetch = [&](int c, int s) {
        int k0 = c * KCH;
        const float* bs = Bw + (size_t)colBase * K + k0;
#pragma unroll
        for (int i = 0; i < 2; ++i) {
            int idx = tid + (i << 8);
            int row = idx >> 2, seg = idx & 3;
            bfb[s][i] = *reinterpret_cast<const float4*>(bs + (size_t)row * K + seg * 4);
        }
        if (AMODE == 1) {
            const __half* ah = (const __half*)Av + (size_t)rowBase * K + k0;
#pragma unroll
            for (int i = 0; i < 2; ++i) {
                int idx = tid + (i << 8);
                int row = idx >> 2, seg = idx & 3;
                ahb[s][i] = *reinterpret_cast<const uint2*>(ah + (size_t)row * K + seg * 4);
            }
        } else {
            const float* as; int ast;
            if (AMODE == 2) {
                if (k0 < 256)      { as = s0 + (size_t)rowBase * 256 + k0;         ast = 256; }
                else if (k0 < 512) { as = s1 + (size_t)rowBase * 256 + (k0 - 256); ast = 256; }
                else if (k0 < 640) { as = s2 + (size_t)rowBase * 128 + (k0 - 512); ast = 128; }
                else               { as = s3 + (size_t)rowBase * 64  + (k0 - 640); ast = 64;  }
            } else {
                as = (const float*)Av + (size_t)rowBase * K + k0; ast = K;
            }
#pragma unroll
            for (int i = 0; i < 2; ++i) {
                int idx = tid + (i << 8);
                int row = idx >> 2, seg = idx & 3;
                afb[s][i] = *reinterpret_cast<const float4*>(as + (size_t)row * ast + seg * 4);
            }
        }
    };
    // ---- store buffer set s into smem stage st
    auto stsbuf = [&](int s, int st) {
        __half* Ab = sm + st * STAGE_HALFS;
        __half* Bb = Ab + TILE_HALFS;
#pragma unroll
        for (int i = 0; i < 2; ++i) {
            int idx = tid + (i << 8);
            int row = idx >> 2, seg = idx & 3;
            uint2 u;
            if (AMODE == 1) {
                u = ahb[s][i];
            } else {
                __half2 h0 = __floats2half2_rn(afb[s][i].x, afb[s][i].y);
                __half2 h1 = __floats2half2_rn(afb[s][i].z, afb[s][i].w);
                u.x = *(uint32_t*)&h0; u.y = *(uint32_t*)&h1;
            }
            *reinterpret_cast<uint2*>(Ab + row * ROWH + seg * 4) = u;
            __half2 g0 = __floats2half2_rn(bfb[s][i].x, bfb[s][i].y);
            __half2 g1 = __floats2half2_rn(bfb[s][i].z, bfb[s][i].w);
            uint2 v; v.x = *(uint32_t*)&g0; v.y = *(uint32_t*)&g1;
            *reinterpret_cast<uint2*>(Bb + row * ROWH + seg * 4) = v;
        }
    };

    fetch(0, 0);
    for (int c = 0; c < Cn; ++c) {
        stsbuf(c & 1, c & 1);
        __syncthreads();
        if (c + 1 < Cn) fetch(c + 1, (c + 1) & 1);

        const uint32_t Ab = sb + (uint32_t)(c & 1) * STAGE_HALFS * 2;
        const uint32_t Bb = Ab + TILE_HALFS * 2;

        uint32_t af[4][4], bf[4][2];
        // A frags: x4 per m16 tile. lane -> matrix l>>3, row l&7.
        // m0: rows r0..+7 k0 ; m1: rows r0+8..+15 k0 ; m2: r0.. k8 ; m3: r0+8.. k8
        {
            int arw = (lane & 7) + ((lane >> 3) & 1) * 8;
            int acl = (lane >> 4) * 8;
#pragma unroll
            for (int mt = 0; mt < 4; mt++) {
                int r0 = wm * 64 + mt * 16;
                ldsm4(af[mt], Ab + (uint32_t)((r0 + arw) * ROWH + acl) * 2);
            }
        }
        // B frags: x2 per n8 tile. lanes 0-7 -> rows n0..+7 col0; 8-15 -> col8.
        {
            int l = lane & 15;
            int brw = l & 7;
            int bcl = (l >> 3) * 8;
#pragma unroll
            for (int nt = 0; nt < 4; nt++) {
                int n0 = wn * 32 + nt * 8;
                ldsm2(bf[nt], Bb + (uint32_t)((n0 + brw) * ROWH + bcl) * 2);
            }
        }
#pragma unroll
        for (int mt = 0; mt < 4; mt++)
#pragma unroll
            for (int nt = 0; nt < 4; nt++)
                mma16(acc[mt][nt], af[mt], bf[nt]);
        __syncthreads();
    }

    // ---- epilogue
#pragma unroll
    for (int mt = 0; mt < 4; mt++) {
        int r0 = rowBase + wm * 64 + mt * 16 + (lane >> 2);
        int id0 = 0, id1 = 0;
        if (OMODE == 2) { id0 = load_id(idsv, r0); id1 = load_id(idsv, r0 + 8); }
#pragma unroll
        for (int nt = 0; nt < 4; nt++) {
            int c0 = colBase + wn * 32 + nt * 8 + (lane & 3) * 2;
            float bv0 = bias[c0], bv1 = bias[c0 + 1];
            float o00 = acc[mt][nt][0] + bv0, o01 = acc[mt][nt][1] + bv1;
            float o10 = acc[mt][nt][2] + bv0, o11 = acc[mt][nt][3] + bv1;
            if (relu) {
                o00 = fmaxf(o00, 0.f); o01 = fmaxf(o01, 0.f);
                o10 = fmaxf(o10, 0.f); o11 = fmaxf(o11, 0.f);
            }
            if (OMODE == 0) {
                float* Co = (float*)Cv;
                *reinterpret_cast<float2*>(Co + (size_t)r0 * Nld + c0) = make_float2(o00, o01);
                *reinterpret_cast<float2*>(Co + (size_t)(r0 + 8) * Nld + c0) = make_float2(o10, o11);
            } else if (OMODE == 1) {
                __half* Ch = (__half*)Cv;
                *reinterpret_cast<__half2*>(Ch + (size_t)r0 * Nld + c0) = __floats2half2_rn(o00, o01);
                *reinterpret_cast<__half2*>(Ch + (size_t)(r0 + 8) * Nld + c0) = __floats2half2_rn(o10, o11);
            } else {
                atomicAdd(&g_sums[(size_t)id0 * MSGD + c0],     o00);
                atomicAdd(&g_sums[(size_t)id0 * MSGD + c0 + 1], o01);
                atomicAdd(&g_sums[(size_t)id1 * MSGD + c0],     o10);
                atomicAdd(&g_sums[(size_t)id1 * MSGD + c0 + 1], o11);
            }
        }
    }
}

// ---------------- GRU gates + output ----------------------------------------
__global__ void k_gate(const float* __restrict__ dstm, float* __restrict__ out,
                       int mem_off) {
    int idx = blockIdx.x * blockDim.x + threadIdx.x;  // NN*DM
    int u = idx >> 8;
    int c = idx & 255;
    const float* gi = g_gih + (size_t)u * (3 * DM);
    const float* gh = g_ghh + (size_t)u * (3 * DM);
    float r = 1.0f / (1.0f + expf(-(gi[c] + gh[c])));
    float z = 1.0f / (1.0f + expf(-(gi[256 + c] + gh[256 + c])));
    float n = tanhf(gi[512 + c] + r * gh[512 + c]);
    float prev = dstm[idx];
    out[mem_off + idx] = (1.0f - z) * n + z * prev;
}

// ---------------- launch -----------------------------------------------------
extern "C" void kernel_launch(void* const* d_in, const int* in_sizes, int n_in,
                              void* d_out, int out_size)
{
    const float* rel_time = (const float*)d_in[0];
    const float* srcm     = (const float*)d_in[1];
    const float* dstm     = (const float*)d_in[2];
    const float* edgef    = (const float*)d_in[3];
    const void*  idsv     =               d_in[4];
    const float* tw       = (const float*)d_in[5];
    const float* tb       = (const float*)d_in[6];
    const float* w1       = (const float*)d_in[7];
    const float* b1       = (const float*)d_in[8];
    const float* w2       = (const float*)d_in[9];
    const float* b2       = (const float*)d_in[10];
    const float* wih      = (const float*)d_in[11];
    const float* whh      = (const float*)d_in[12];
    const float* bih      = (const float*)d_in[13];
    const float* bhh      = (const float*)d_in[14];
    float* out = (float*)d_out;

    int write_ids = (out_size >= NN + NN * DM) ? 1 : 0;
    int mem_off   = write_ids ? NN : 0;

    void *p_hh; float *p_agg, *p_gih, *p_ghh, *p_tenc;
    cudaGetSymbolAddress(&p_hh, g_hh);
    cudaGetSymbolAddress((void**)&p_agg,  g_agg);
    cudaGetSymbolAddress((void**)&p_gih,  g_gih);
    cudaGetSymbolAddress((void**)&p_ghh,  g_ghh);
    cudaGetSymbolAddress((void**)&p_tenc, g_tenc);

    k_detect<<<1, 32>>>((const int*)idsv);
    k_zero<<<(NN * MSGD) / 256, 256>>>(out, write_ids);
    k_count<<<E_NUM / 256, 256>>>(idsv);
    k_scan<<<1, 1024>>>(out, write_ids);
    k_tenc<<<(E_NUM * 64) / 256, 256>>>(rel_time, tw, tb);

    // GEMM1: h = relu([src|dst|edge|t_enc] @ w1^T + b1) -> fp16   131072x512, K=704
    mma_gemm<2, 1><<<dim3(HIDN / 128, E_NUM / 128), 256>>>(
        nullptr, w1, b1, p_hh, 704, HIDN, 1, nullptr, srcm, dstm, edgef, p_tenc);

    // GEMM2: msg = h @ w2^T + b2, scatter-atomic into g_sums     131072x256, K=512
    mma_gemm<1, 2><<<dim3(MSGD / 128, E_NUM / 128), 256>>>(
        p_hh, w2, b2, nullptr, 512, MSGD, 0, idsv, nullptr, nullptr, nullptr, nullptr);

    k_agg<<<(NN * 64) / 256, 256>>>();

    // GRU: gi = agg @ wih^T + bih ; gh = prev @ whh^T + bhh       32768x768, K=256
    mma_gemm<0, 0><<<dim3((3 * DM) / 128, NN / 128), 256>>>(
        p_agg, wih, bih, p_gih, 256, 3 * DM, 0, nullptr, nullptr, nullptr, nullptr, nullptr);
    mma_gemm<0, 0><<<dim3((3 * DM) / 128, NN / 128), 256>>>(
        dstm, whh, bhh, p_ghh, 256, 3 * DM, 0, nullptr, nullptr, nullptr, nullptr, nullptr);

    k_gate<<<(NN * DM) / 256, 256>>>(dstm, out, mem_off);
}

// round 14
// speedup vs baseline: 1.0054x; 1.0040x over previous
#include <cuda_runtime.h>
#include <cuda_fp16.h>
#include <math.h>
#include <stdint.h>

#define E_NUM  131072
#define NN     32768
#define DM     256
#define HIDN   512
#define MSGD   256

// ---------------- scratch (static device globals; no allocation) ----------
__device__ __half g_hh [(size_t)E_NUM * HIDN];   // 134 MB (h, fp16)
__device__ float g_tenc[(size_t)E_NUM * 64];     // 33.5 MB
__device__ float g_sums[(size_t)NN * MSGD];      // 33.5 MB (indexed by id)
__device__ float g_agg [(size_t)NN * MSGD];      // 33.5 MB (unique-slot order)
__device__ float g_gih [(size_t)NN * 3 * DM];    // 100 MB
__device__ float g_ghh [(size_t)NN * 3 * DM];    // 100 MB
__device__ int   g_cnt [NN];
__device__ int   g_uid [NN];
__device__ int   g_is64;

// ---------------- helpers ---------------------------------------------------
__device__ __forceinline__ uint32_t smem_u32(const void* p) {
    uint32_t a;
    asm("{ .reg .u64 t; cvta.to.shared.u64 t, %1; cvt.u32.u64 %0, t; }"
        : "=r"(a) : "l"(p));
    return a;
}
__device__ __forceinline__ void mma16(float* d, const uint32_t* a, const uint32_t* b) {
    asm volatile("mma.sync.aligned.m16n8k16.row.col.f32.f16.f16.f32 "
                 "{%0,%1,%2,%3}, {%4,%5,%6,%7}, {%8,%9}, {%0,%1,%2,%3};"
                 : "+f"(d[0]), "+f"(d[1]), "+f"(d[2]), "+f"(d[3])
                 : "r"(a[0]), "r"(a[1]), "r"(a[2]), "r"(a[3]),
                   "r"(b[0]), "r"(b[1]));
}
__device__ __forceinline__ void ldsm4(uint32_t* r, uint32_t addr) {
    asm volatile("ldmatrix.sync.aligned.m8n8.x4.shared.b16 {%0,%1,%2,%3}, [%4];"
                 : "=r"(r[0]), "=r"(r[1]), "=r"(r[2]), "=r"(r[3]) : "r"(addr));
}
__device__ __forceinline__ void ldsm2(uint32_t* r, uint32_t addr) {
    asm volatile("ldmatrix.sync.aligned.m8n8.x2.shared.b16 {%0,%1}, [%2];"
                 : "=r"(r[0]), "=r"(r[1]) : "r"(addr));
}

// ---------------- dtype detector for dst_ids (int32 vs int64) -------------
__global__ void k_detect(const int* ids32) {
    if (threadIdx.x == 0 && blockIdx.x == 0) {
        int z = 0;
        for (int i = 1; i < 64; i += 2) z |= ids32[i];
        g_is64 = (z == 0) ? 1 : 0;
    }
}
__device__ __forceinline__ int load_id(const void* idsv, int e) {
    if (g_is64) return (int)((const long long*)idsv)[e];
    return ((const int*)idsv)[e];
}

// ---------------- per-launch init ------------------------------------------
__global__ void k_zero(float* out, int write_ids) {
    int idx = blockIdx.x * blockDim.x + threadIdx.x;  // NN*MSGD threads
    g_sums[idx] = 0.0f;
    if (idx < NN) {
        g_cnt[idx] = 0;
        g_uid[idx] = NN;
        if (write_ids) out[idx] = (float)NN;
    }
}

// ---------------- time encoding --------------------------------------------
__global__ void k_tenc(const float* __restrict__ rt, const float* __restrict__ tw,
                       const float* __restrict__ tb) {
    int idx = blockIdx.x * blockDim.x + threadIdx.x;  // E*64
    int e = idx >> 6, j = idx & 63;
    g_tenc[idx] = cosf(fmaf(rt[e], tw[j], tb[j]));
}

// ---------------- per-id counts --------------------------------------------
__global__ void k_count(const void* idsv) {
    int e = blockIdx.x * blockDim.x + threadIdx.x;
    if (e < E_NUM) atomicAdd(&g_cnt[load_id(idsv, e)], 1);
}

// ---------------- sorted-unique (ballot-based, coalesced) -------------------
__global__ void k_scan(float* out, int write_ids) {
    __shared__ uint32_t masks[32][32];
    __shared__ int wtot[32];
    int lane = threadIdx.x & 31, wid = threadIdx.x >> 5;
    int tot = 0;
#pragma unroll
    for (int i = 0; i < 32; i++) {
        int id = wid * 1024 + i * 32 + lane;
        uint32_t m = __ballot_sync(0xFFFFFFFFu, g_cnt[id] > 0);
        masks[wid][i] = m;
        tot += __popc(m);
    }
    if (lane == 0) wtot[wid] = tot;
    __syncthreads();
    if (wid == 0) {
        int w = wtot[lane], v = w;
#pragma unroll
        for (int off = 1; off < 32; off <<= 1) {
            int t = __shfl_up_sync(0xFFFFFFFFu, v, off);
            if (lane >= off) v += t;
        }
        wtot[lane] = v - w;   // exclusive
    }
    __syncthreads();
    int r = wtot[wid];
#pragma unroll
    for (int i = 0; i < 32; i++) {
        uint32_t m = masks[wid][i];
        int id = wid * 1024 + i * 32 + lane;
        if (m & (1u << lane)) {
            int rk = r + __popc(m & ((1u << lane) - 1u));
            g_uid[rk] = id;
            if (write_ids) out[rk] = (float)id;
        }
        r += __popc(m);
    }
}

// ---------------- agg = sums/count in unique-slot order ---------------------
__global__ void k_agg() {
    int idx = blockIdx.x * blockDim.x + threadIdx.x;  // NN*64
    int u = idx >> 6;
    int c4 = (idx & 63) << 2;
    int id = g_uid[u];
    float4 o = make_float4(0.f, 0.f, 0.f, 0.f);
    if (id < NN) {
        float cnt = (float)g_cnt[id];
        float4 s = *reinterpret_cast<const float4*>(g_sums + (size_t)id * MSGD + c4);
        o.x = s.x / cnt; o.y = s.y / cnt; o.z = s.z / cnt; o.w = s.w / cnt;
    }
    *reinterpret_cast<float4*>(g_agg + (size_t)u * MSGD + c4) = o;
}

// ---------------- fp16 mma.sync GEMM: C = A(MxK) * B(NxK)^T + bias ----------
// CTA 128x128, 8 warps (2x4), warp tile 64x32 of m16n8k16 frags, KCH=16.
// Smem rows: 40 halves (80B stride) -> conflict-free ldmatrix.
// AMODE: 0 = f32 A, 1 = half A, 2 = concat f32 sources.
// OMODE: 0 = f32 store, 1 = half store (+relu), 2 = scatter-atomic into g_sums.
#define KCH   16
#define ROWH  40
#define TILE_HALFS (128 * ROWH)                  // 5120 halves
#define STAGE_HALFS (2 * TILE_HALFS)             // A + B
#define SMEM_HALFS  (2 * STAGE_HALFS)            // 2 stages = 40960 B

template <int AMODE, int OMODE>
__global__ void __launch_bounds__(256, 2)
mma_gemm(const void* __restrict__ Av, const float* __restrict__ Bw,
         const float* __restrict__ bias, void* __restrict__ Cv,
         int K, int Nld, int relu, const void* __restrict__ idsv,
         const float* __restrict__ s0, const float* __restrict__ s1,
         const float* __restrict__ s2, const float* __restrict__ s3)
{
    __shared__ __half sm[SMEM_HALFS];
    const int tid  = threadIdx.x;
    const int lane = tid & 31;
    const int wid  = tid >> 5;
    const int wm   = wid >> 2;      // 0..1  (64-row slabs)
    const int wn   = wid & 3;       // 0..3  (32-col slabs)
    const int rowBase = blockIdx.y * 128;
    const int colBase = blockIdx.x * 128;
    const uint32_t sb = smem_u32(sm);

    float acc[4][4][4];
#pragma unroll
    for (int mt = 0; mt < 4; mt++)
#pragma unroll
        for (int nt = 0; nt < 4; nt++)
#pragma unroll
            for (int r = 0; r < 4; r++) acc[mt][nt][r] = 0.0f;

    const int Cn = K / KCH;
    const int arow = tid >> 2, aseg = tid & 3;            // i=0 plane
    const int brow = (tid + 256) >> 2;                    // wait: B uses same pattern

    // prefetch buffers (ping-pong)
    float4 afb[2][2], bfb[2][2];
    uint2  ahb[2][2];

    // ---- loader: fetch chunk c into buffer set s
    auto fetch = [&](int c, int s) {
        int k0 = c * KCH;
        const float* bs = Bw + (size_t)colBase * K + k0;
#pragma unroll
        for (int i = 0; i < 2; ++i) {
            int idx = tid + (i << 8);
            int row = idx >> 2, seg = idx & 3;
            bfb[s][i] = *reinterpret_cast<const float4*>(bs + (size_t)row * K + seg * 4);
        }
        if (AMODE == 1) {
            const __half* ah = (const __half*)Av + (size_t)rowBase * K + k0;
#pragma unroll
            for (int i = 0; i < 2; ++i) {
                int idx = tid + (i << 8);
                int row = idx >> 2, seg = idx & 3;
                ahb[s][i] = *reinterpret_cast<const uint2*>(ah + (size_t)row * K + seg * 4);
            }
        } else {
            const float* as; int ast;
            if (AMODE == 2) {
                if (k0 < 256)      { as = s0 + (size_t)rowBase * 256 + k0;         ast = 256; }
                else if (k0 < 512) { as = s1 + (size_t)rowBase * 256 + (k0 - 256); ast = 256; }
                else if (k0 < 640) { as = s2 + (size_t)rowBase * 128 + (k0 - 512); ast = 128; }
                else               { as = s3 + (size_t)rowBase * 64  + (k0 - 640); ast = 64;  }
            } else {
                as = (const float*)Av + (size_t)rowBase * K + k0; ast = K;
            }
#pragma unroll
            for (int i = 0; i < 2; ++i) {
                int idx = tid + (i << 8);
                int row = idx >> 2, seg = idx & 3;
                afb[s][i] = *reinterpret_cast<const float4*>(as + (size_t)row * ast + seg * 4);
            }
        }
    };
    // ---- store buffer set s into smem stage st
    auto stsbuf = [&](int s, int st) {
        __half* Ab = sm + st * STAGE_HALFS;
        __half* Bb = Ab + TILE_HALFS;
#pragma unroll
        for (int i = 0; i < 2; ++i) {
            int idx = tid + (i << 8);
            int row = idx >> 2, seg = idx & 3;
            uint2 u;
            if (AMODE == 1) {
                u = ahb[s][i];
            } else {
                __half2 h0 = __floats2half2_rn(afb[s][i].x, afb[s][i].y);
                __half2 h1 = __floats2half2_rn(afb[s][i].z, afb[s][i].w);
                u.x = *(uint32_t*)&h0; u.y = *(uint32_t*)&h1;
            }
            *reinterpret_cast<uint2*>(Ab + row * ROWH + seg * 4) = u;
            __half2 g0 = __floats2half2_rn(bfb[s][i].x, bfb[s][i].y);
            __half2 g1 = __floats2half2_rn(bfb[s][i].z, bfb[s][i].w);
            uint2 v; v.x = *(uint32_t*)&g0; v.y = *(uint32_t*)&g1;
            *reinterpret_cast<uint2*>(Bb + row * ROWH + seg * 4) = v;
        }
    };

    fetch(0, 0);
    for (int c = 0; c < Cn; ++c) {
        stsbuf(c & 1, c & 1);
        __syncthreads();
        if (c + 1 < Cn) fetch(c + 1, (c + 1) & 1);

        const uint32_t Ab = sb + (uint32_t)(c & 1) * STAGE_HALFS * 2;
        const uint32_t Bb = Ab + TILE_HALFS * 2;

        uint32_t af[4][4], bf[4][2];
        // A frags: x4 per m16 tile. lane -> matrix l>>3, row l&7.
        // m0: rows r0..+7 k0 ; m1: rows r0+8..+15 k0 ; m2: r0.. k8 ; m3: r0+8.. k8
        {
            int arw = (lane & 7) + ((lane >> 3) & 1) * 8;
            int acl = (lane >> 4) * 8;
#pragma unroll
            for (int mt = 0; mt < 4; mt++) {
                int r0 = wm * 64 + mt * 16;
                ldsm4(af[mt], Ab + (uint32_t)((r0 + arw) * ROWH + acl) * 2);
            }
        }
        // B frags: x2 per n8 tile. lanes 0-7 -> rows n0..+7 col0; 8-15 -> col8.
        {
            int l = lane & 15;
            int brw = l & 7;
            int bcl = (l >> 3) * 8;
#pragma unroll
            for (int nt = 0; nt < 4; nt++) {
                int n0 = wn * 32 + nt * 8;
                ldsm2(bf[nt], Bb + (uint32_t)((n0 + brw) * ROWH + bcl) * 2);
            }
        }
#pragma unroll
        for (int mt = 0; mt < 4; mt++)
#pragma unroll
            for (int nt = 0; nt < 4; nt++)
                mma16(acc[mt][nt], af[mt], bf[nt]);
        __syncthreads();
    }

    // ---- epilogue
#pragma unroll
    for (int mt = 0; mt < 4; mt++) {
        int r0 = rowBase + wm * 64 + mt * 16 + (lane >> 2);
        int id0 = 0, id1 = 0;
        if (OMODE == 2) { id0 = load_id(idsv, r0); id1 = load_id(idsv, r0 + 8); }
#pragma unroll
        for (int nt = 0; nt < 4; nt++) {
            int c0 = colBase + wn * 32 + nt * 8 + (lane & 3) * 2;
            float bv0 = bias[c0], bv1 = bias[c0 + 1];
            float o00 = acc[mt][nt][0] + bv0, o01 = acc[mt][nt][1] + bv1;
            float o10 = acc[mt][nt][2] + bv0, o11 = acc[mt][nt][3] + bv1;
            if (relu) {
                o00 = fmaxf(o00, 0.f); o01 = fmaxf(o01, 0.f);
                o10 = fmaxf(o10, 0.f); o11 = fmaxf(o11, 0.f);
            }
            if (OMODE == 0) {
                float* Co = (float*)Cv;
                *reinterpret_cast<float2*>(Co + (size_t)r0 * Nld + c0) = make_float2(o00, o01);
                *reinterpret_cast<float2*>(Co + (size_t)(r0 + 8) * Nld + c0) = make_float2(o10, o11);
            } else if (OMODE == 1) {
                __half* Ch = (__half*)Cv;
                *reinterpret_cast<__half2*>(Ch + (size_t)r0 * Nld + c0) = __floats2half2_rn(o00, o01);
                *reinterpret_cast<__half2*>(Ch + (size_t)(r0 + 8) * Nld + c0) = __floats2half2_rn(o10, o11);
            } else {
                atomicAdd(&g_sums[(size_t)id0 * MSGD + c0],     o00);
                atomicAdd(&g_sums[(size_t)id0 * MSGD + c0 + 1], o01);
                atomicAdd(&g_sums[(size_t)id1 * MSGD + c0],     o10);
                atomicAdd(&g_sums[(size_t)id1 * MSGD + c0 + 1], o11);
            }
        }
    }
}

// ---------------- GRU gates + output ----------------------------------------
__global__ void k_gate(const float* __restrict__ dstm, float* __restrict__ out,
                       int mem_off) {
    int idx = blockIdx.x * blockDim.x + threadIdx.x;  // NN*DM
    int u = idx >> 8;
    int c = idx & 255;
    const float* gi = g_gih + (size_t)u * (3 * DM);
    const float* gh = g_ghh + (size_t)u * (3 * DM);
    float r = 1.0f / (1.0f + expf(-(gi[c] + gh[c])));
    float z = 1.0f / (1.0f + expf(-(gi[256 + c] + gh[256 + c])));
    float n = tanhf(gi[512 + c] + r * gh[512 + c]);
    float prev = dstm[idx];
    out[mem_off + idx] = (1.0f - z) * n + z * prev;
}

// ---------------- launch -----------------------------------------------------
extern "C" void kernel_launch(void* const* d_in, const int* in_sizes, int n_in,
                              void* d_out, int out_size)
{
    const float* rel_time = (const float*)d_in[0];
    const float* srcm     = (const float*)d_in[1];
    const float* dstm     = (const float*)d_in[2];
    const float* edgef    = (const float*)d_in[3];
    const void*  idsv     =               d_in[4];
    const float* tw       = (const float*)d_in[5];
    const float* tb       = (const float*)d_in[6];
    const float* w1       = (const float*)d_in[7];
    const float* b1       = (const float*)d_in[8];
    const float* w2       = (const float*)d_in[9];
    const float* b2       = (const float*)d_in[10];
    const float* wih      = (const float*)d_in[11];
    const float* whh      = (const float*)d_in[12];
    const float* bih      = (const float*)d_in[13];
    const float* bhh      = (const float*)d_in[14];
    float* out = (float*)d_out;

    int write_ids = (out_size >= NN + NN * DM) ? 1 : 0;
    int mem_off   = write_ids ? NN : 0;

    void *p_hh; float *p_agg, *p_gih, *p_ghh, *p_tenc;
    cudaGetSymbolAddress(&p_hh, g_hh);
    cudaGetSymbolAddress((void**)&p_agg,  g_agg);
    cudaGetSymbolAddress((void**)&p_gih,  g_gih);
    cudaGetSymbolAddress((void**)&p_ghh,  g_ghh);
    cudaGetSymbolAddress((void**)&p_tenc, g_tenc);

    k_detect<<<1, 32>>>((const int*)idsv);
    k_zero<<<(NN * MSGD) / 256, 256>>>(out, write_ids);
    k_count<<<E_NUM / 256, 256>>>(idsv);
    k_scan<<<1, 1024>>>(out, write_ids);
    k_tenc<<<(E_NUM * 64) / 256, 256>>>(rel_time, tw, tb);

    // GEMM1: h = relu([src|dst|edge|t_enc] @ w1^T + b1) -> fp16   131072x512, K=704
    mma_gemm<2, 1><<<dim3(HIDN / 128, E_NUM / 128), 256>>>(
        nullptr, w1, b1, p_hh, 704, HIDN, 1, nullptr, srcm, dstm, edgef, p_tenc);

    // GEMM2: msg = h @ w2^T + b2, scatter-atomic into g_sums     131072x256, K=512
    mma_gemm<1, 2><<<dim3(MSGD / 128, E_NUM / 128), 256>>>(
        p_hh, w2, b2, nullptr, 512, MSGD, 0, idsv, nullptr, nullptr, nullptr, nullptr);

    k_agg<<<(NN * 64) / 256, 256>>>();

    // GRU: gi = agg @ wih^T + bih ; gh = prev @ whh^T + bhh       32768x768, K=256
    mma_gemm<0, 0><<<dim3((3 * DM) / 128, NN / 128), 256>>>(
        p_agg, wih, bih, p_gih, 256, 3 * DM, 0, nullptr, nullptr, nullptr, nullptr, nullptr);
    mma_gemm<0, 0><<<dim3((3 * DM) / 128, NN / 128), 256>>>(
        dstm, whh, bhh, p_ghh, 256, 3 * DM, 0, nullptr, nullptr, nullptr, nullptr, nullptr);

    k_gate<<<(NN * DM) / 256, 256>>>(dstm, out, mem_off);
}

// round 15
// speedup vs baseline: 1.0069x; 1.0015x over previous
#include <cuda_runtime.h>
#include <cuda_fp16.h>
#include <math.h>
#include <stdint.h>

#define E_NUM  131072
#define NN     32768
#define DM     256
#define HIDN   512
#define MSGD   256

// ---------------- scratch (static device globals; no allocation) ----------
__device__ __half g_hh [(size_t)E_NUM * HIDN];   // 134 MB (h, fp16)
__device__ float g_tenc[(size_t)E_NUM * 64];     // 33.5 MB
__device__ float g_sums[(size_t)NN * MSGD];      // 33.5 MB (indexed by id)
__device__ float g_agg [(size_t)NN * MSGD];      // 33.5 MB (unique-slot order)
__device__ float g_gih [(size_t)NN * 3 * DM];    // 100 MB
__device__ float g_ghh [(size_t)NN * 3 * DM];    // 100 MB
__device__ int   g_cnt [NN];
__device__ int   g_uid [NN];
__device__ int   g_is64;

// ---------------- helpers ---------------------------------------------------
__device__ __forceinline__ uint32_t smem_u32(const void* p) {
    uint32_t a;
    asm("{ .reg .u64 t; cvta.to.shared.u64 t, %1; cvt.u32.u64 %0, t; }"
        : "=r"(a) : "l"(p));
    return a;
}
__device__ __forceinline__ void mma16(float* d, const uint32_t* a, const uint32_t* b) {
    asm volatile("mma.sync.aligned.m16n8k16.row.col.f32.f16.f16.f32 "
                 "{%0,%1,%2,%3}, {%4,%5,%6,%7}, {%8,%9}, {%0,%1,%2,%3};"
                 : "+f"(d[0]), "+f"(d[1]), "+f"(d[2]), "+f"(d[3])
                 : "r"(a[0]), "r"(a[1]), "r"(a[2]), "r"(a[3]),
                   "r"(b[0]), "r"(b[1]));
}
__device__ __forceinline__ void ldsm4(uint32_t* r, uint32_t addr) {
    asm volatile("ldmatrix.sync.aligned.m8n8.x4.shared.b16 {%0,%1,%2,%3}, [%4];"
                 : "=r"(r[0]), "=r"(r[1]), "=r"(r[2]), "=r"(r[3]) : "r"(addr));
}
__device__ __forceinline__ void ldsm2(uint32_t* r, uint32_t addr) {
    asm volatile("ldmatrix.sync.aligned.m8n8.x2.shared.b16 {%0,%1}, [%2];"
                 : "=r"(r[0]), "=r"(r[1]) : "r"(addr));
}

// ---------------- dtype detector for dst_ids (int32 vs int64) -------------
__global__ void k_detect(const int* ids32) {
    if (threadIdx.x == 0 && blockIdx.x == 0) {
        int z = 0;
        for (int i = 1; i < 64; i += 2) z |= ids32[i];
        g_is64 = (z == 0) ? 1 : 0;
    }
}
__device__ __forceinline__ int load_id(const void* idsv, int e) {
    if (g_is64) return (int)((const long long*)idsv)[e];
    return ((const int*)idsv)[e];
}

// ---------------- per-launch init ------------------------------------------
__global__ void k_zero(float* out, int write_ids) {
    int idx = blockIdx.x * blockDim.x + threadIdx.x;  // NN*MSGD threads
    g_sums[idx] = 0.0f;
    if (idx < NN) {
        g_cnt[idx] = 0;
        g_uid[idx] = NN;
        if (write_ids) out[idx] = (float)NN;
    }
}

// ---------------- time encoding --------------------------------------------
__global__ void k_tenc(const float* __restrict__ rt, const float* __restrict__ tw,
                       const float* __restrict__ tb) {
    int idx = blockIdx.x * blockDim.x + threadIdx.x;  // E*64
    int e = idx >> 6, j = idx & 63;
    g_tenc[idx] = cosf(fmaf(rt[e], tw[j], tb[j]));
}

// ---------------- per-id counts --------------------------------------------
__global__ void k_count(const void* idsv) {
    int e = blockIdx.x * blockDim.x + threadIdx.x;
    if (e < E_NUM) atomicAdd(&g_cnt[load_id(idsv, e)], 1);
}

// ---------------- sorted-unique (ballot-based, coalesced) -------------------
__global__ void k_scan(float* out, int write_ids) {
    __shared__ uint32_t masks[32][32];
    __shared__ int wtot[32];
    int lane = threadIdx.x & 31, wid = threadIdx.x >> 5;
    int tot = 0;
#pragma unroll
    for (int i = 0; i < 32; i++) {
        int id = wid * 1024 + i * 32 + lane;
        uint32_t m = __ballot_sync(0xFFFFFFFFu, g_cnt[id] > 0);
        masks[wid][i] = m;
        tot += __popc(m);
    }
    if (lane == 0) wtot[wid] = tot;
    __syncthreads();
    if (wid == 0) {
        int w = wtot[lane], v = w;
#pragma unroll
        for (int off = 1; off < 32; off <<= 1) {
            int t = __shfl_up_sync(0xFFFFFFFFu, v, off);
            if (lane >= off) v += t;
        }
        wtot[lane] = v - w;   // exclusive
    }
    __syncthreads();
    int r = wtot[wid];
#pragma unroll
    for (int i = 0; i < 32; i++) {
        uint32_t m = masks[wid][i];
        int id = wid * 1024 + i * 32 + lane;
        if (m & (1u << lane)) {
            int rk = r + __popc(m & ((1u << lane) - 1u));
            g_uid[rk] = id;
            if (write_ids) out[rk] = (float)id;
        }
        r += __popc(m);
    }
}

// ---------------- agg = sums/count in unique-slot order ---------------------
__global__ void k_agg() {
    int idx = blockIdx.x * blockDim.x + threadIdx.x;  // NN*64
    int u = idx >> 6;
    int c4 = (idx & 63) << 2;
    int id = g_uid[u];
    float4 o = make_float4(0.f, 0.f, 0.f, 0.f);
    if (id < NN) {
        float cnt = (float)g_cnt[id];
        float4 s = *reinterpret_cast<const float4*>(g_sums + (size_t)id * MSGD + c4);
        o.x = s.x / cnt; o.y = s.y / cnt; o.z = s.z / cnt; o.w = s.w / cnt;
    }
    *reinterpret_cast<float4*>(g_agg + (size_t)u * MSGD + c4) = o;
}

// ---------------- fp16 mma.sync GEMM: C = A(MxK) * B(NxK)^T + bias ----------
// CTA 128x128, 8 warps (2x4), warp tile 64x32 of m16n8k16 frags, KCH=16.
// Smem rows: 40 halves (80B stride) -> conflict-free ldmatrix.
// AMODE: 0 = f32 A, 1 = half A, 2 = concat f32 sources.
// OMODE: 0 = f32 store, 1 = half store (+relu), 2 = scatter-atomic into g_sums.
#define KCH   16
#define ROWH  40
#define TILE_HALFS (128 * ROWH)                  // 5120 halves
#define STAGE_HALFS (2 * TILE_HALFS)             // A + B
#define SMEM_HALFS  (2 * STAGE_HALFS)            // 2 stages = 40960 B

template <int AMODE, int OMODE>
__global__ void __launch_bounds__(256, 2)
mma_gemm(const void* __restrict__ Av, const float* __restrict__ Bw,
         const float* __restrict__ bias, void* __restrict__ Cv,
         int K, int Nld, int relu, const void* __restrict__ idsv,
         const float* __restrict__ s0, const float* __restrict__ s1,
         const float* __restrict__ s2, const float* __restrict__ s3)
{
    __shared__ __half sm[SMEM_HALFS];
    const int tid  = threadIdx.x;
    const int lane = tid & 31;
    const int wid  = tid >> 5;
    const int wm   = wid >> 2;      // 0..1  (64-row slabs)
    const int wn   = wid & 3;       // 0..3  (32-col slabs)
    const int rowBase = blockIdx.y * 128;
    const int colBase = blockIdx.x * 128;
    const uint32_t sb = smem_u32(sm);

    float acc[4][4][4];
#pragma unroll
    for (int mt = 0; mt < 4; mt++)
#pragma unroll
        for (int nt = 0; nt < 4; nt++)
#pragma unroll
            for (int r = 0; r < 4; r++) acc[mt][nt][r] = 0.0f;

    const int Cn = K / KCH;
    const int arow = tid >> 2, aseg = tid & 3;            // i=0 plane
    const int brow = (tid + 256) >> 2;                    // wait: B uses same pattern

    // prefetch buffers (ping-pong)
    float4 afb[2][2], bfb[2][2];
    uint2  ahb[2][2];

    // ---- loader: fetch chunk c into buffer set s
    auto fetch = [&](int c, int s) {
        int k0 = c * KCH;
        const float* bs = Bw + (size_t)colBase * K + k0;
#pragma unroll
        for (int i = 0; i < 2; ++i) {
            int idx = tid + (i << 8);
            int row = idx >> 2, seg = idx & 3;
            bfb[s][i] = *reinterpret_cast<const float4*>(bs + (size_t)row * K + seg * 4);
        }
        if (AMODE == 1) {
            const __half* ah = (const __half*)Av + (size_t)rowBase * K + k0;
#pragma unroll
            for (int i = 0; i < 2; ++i) {
                int idx = tid + (i << 8);
                int row = idx >> 2, seg = idx & 3;
                ahb[s][i] = *reinterpret_cast<const uint2*>(ah + (size_t)row * K + seg * 4);
            }
        } else {
            const float* as; int ast;
            if (AMODE == 2) {
                if (k0 < 256)      { as = s0 + (size_t)rowBase * 256 + k0;         ast = 256; }
                else if (k0 < 512) { as = s1 + (size_t)rowBase * 256 + (k0 - 256); ast = 256; }
                else if (k0 < 640) { as = s2 + (size_t)rowBase * 128 + (k0 - 512); ast = 128; }
                else               { as = s3 + (size_t)rowBase * 64  + (k0 - 640); ast = 64;  }
            } else {
                as = (const float*)Av + (size_t)rowBase * K + k0; ast = K;
            }
#pragma unroll
            for (int i = 0; i < 2; ++i) {
                int idx = tid + (i << 8);
                int row = idx >> 2, seg = idx & 3;
                afb[s][i] = *reinterpret_cast<const float4*>(as + (size_t)row * ast + seg * 4);
            }
        }
    };
    // ---- store buffer set s into smem stage st
    auto stsbuf = [&](int s, int st) {
        __half* Ab = sm + st * STAGE_HALFS;
        __half* Bb = Ab + TILE_HALFS;
#pragma unroll
        for (int i = 0; i < 2; ++i) {
            int idx = tid + (i << 8);
            int row = idx >> 2, seg = idx & 3;
            uint2 u;
            if (AMODE == 1) {
                u = ahb[s][i];
            } else {
                __half2 h0 = __floats2half2_rn(afb[s][i].x, afb[s][i].y);
                __half2 h1 = __floats2half2_rn(afb[s][i].z, afb[s][i].w);
                u.x = *(uint32_t*)&h0; u.y = *(uint32_t*)&h1;
            }
            *reinterpret_cast<uint2*>(Ab + row * ROWH + seg * 4) = u;
            __half2 g0 = __floats2half2_rn(bfb[s][i].x, bfb[s][i].y);
            __half2 g1 = __floats2half2_rn(bfb[s][i].z, bfb[s][i].w);
            uint2 v; v.x = *(uint32_t*)&g0; v.y = *(uint32_t*)&g1;
            *reinterpret_cast<uint2*>(Bb + row * ROWH + seg * 4) = v;
        }
    };

    fetch(0, 0);
    for (int c = 0; c < Cn; ++c) {
        stsbuf(c & 1, c & 1);
        __syncthreads();
        if (c + 1 < Cn) fetch(c + 1, (c + 1) & 1);

        const uint32_t Ab = sb + (uint32_t)(c & 1) * STAGE_HALFS * 2;
        const uint32_t Bb = Ab + TILE_HALFS * 2;

        uint32_t af[4][4], bf[4][2];
        // A frags: x4 per m16 tile. lane -> matrix l>>3, row l&7.
        // m0: rows r0..+7 k0 ; m1: rows r0+8..+15 k0 ; m2: r0.. k8 ; m3: r0+8.. k8
        {
            int arw = (lane & 7) + ((lane >> 3) & 1) * 8;
            int acl = (lane >> 4) * 8;
#pragma unroll
            for (int mt = 0; mt < 4; mt++) {
                int r0 = wm * 64 + mt * 16;
                ldsm4(af[mt], Ab + (uint32_t)((r0 + arw) * ROWH + acl) * 2);
            }
        }
        // B frags: x2 per n8 tile. lanes 0-7 -> rows n0..+7 col0; 8-15 -> col8.
        {
            int l = lane & 15;
            int brw = l & 7;
            int bcl = (l >> 3) * 8;
#pragma unroll
            for (int nt = 0; nt < 4; nt++) {
                int n0 = wn * 32 + nt * 8;
                ldsm2(bf[nt], Bb + (uint32_t)((n0 + brw) * ROWH + bcl) * 2);
            }
        }
#pragma unroll
        for (int mt = 0; mt < 4; mt++)
#pragma unroll
            for (int nt = 0; nt < 4; nt++)
                mma16(acc[mt][nt], af[mt], bf[nt]);
        __syncthreads();
    }

    // ---- epilogue
#pragma unroll
    for (int mt = 0; mt < 4; mt++) {
        int r0 = rowBase + wm * 64 + mt * 16 + (lane >> 2);
        int id0 = 0, id1 = 0;
        if (OMODE == 2) { id0 = load_id(idsv, r0); id1 = load_id(idsv, r0 + 8); }
#pragma unroll
        for (int nt = 0; nt < 4; nt++) {
            int c0 = colBase + wn * 32 + nt * 8 + (lane & 3) * 2;
            float bv0 = bias[c0], bv1 = bias[c0 + 1];
            float o00 = acc[mt][nt][0] + bv0, o01 = acc[mt][nt][1] + bv1;
            float o10 = acc[mt][nt][2] + bv0, o11 = acc[mt][nt][3] + bv1;
            if (relu) {
                o00 = fmaxf(o00, 0.f); o01 = fmaxf(o01, 0.f);
                o10 = fmaxf(o10, 0.f); o11 = fmaxf(o11, 0.f);
            }
            if (OMODE == 0) {
                float* Co = (float*)Cv;
                *reinterpret_cast<float2*>(Co + (size_t)r0 * Nld + c0) = make_float2(o00, o01);
                *reinterpret_cast<float2*>(Co + (size_t)(r0 + 8) * Nld + c0) = make_float2(o10, o11);
            } else if (OMODE == 1) {
                __half* Ch = (__half*)Cv;
                *reinterpret_cast<__half2*>(Ch + (size_t)r0 * Nld + c0) = __floats2half2_rn(o00, o01);
                *reinterpret_cast<__half2*>(Ch + (size_t)(r0 + 8) * Nld + c0) = __floats2half2_rn(o10, o11);
            } else {
                atomicAdd(&g_sums[(size_t)id0 * MSGD + c0],     o00);
                atomicAdd(&g_sums[(size_t)id0 * MSGD + c0 + 1], o01);
                atomicAdd(&g_sums[(size_t)id1 * MSGD + c0],     o10);
                atomicAdd(&g_sums[(size_t)id1 * MSGD + c0 + 1], o11);
            }
        }
    }
}

// ---------------- GRU gates + output ----------------------------------------
__global__ void k_gate(const float* __restrict__ dstm, float* __restrict__ out,
                       int mem_off) {
    int idx = blockIdx.x * blockDim.x + threadIdx.x;  // NN*DM
    int u = idx >> 8;
    int c = idx & 255;
    const float* gi = g_gih + (size_t)u * (3 * DM);
    const float* gh = g_ghh + (size_t)u * (3 * DM);
    float r = 1.0f / (1.0f + expf(-(gi[c] + gh[c])));
    float z = 1.0f / (1.0f + expf(-(gi[256 + c] + gh[256 + c])));
    float n = tanhf(gi[512 + c] + r * gh[512 + c]);
    float prev = dstm[idx];
    out[mem_off + idx] = (1.0f - z) * n + z * prev;
}

// ---------------- launch -----------------------------------------------------
extern "C" void kernel_launch(void* const* d_in, const int* in_sizes, int n_in,
                              void* d_out, int out_size)
{
    const float* rel_time = (const float*)d_in[0];
    const float* srcm     = (const float*)d_in[1];
    const float* dstm     = (const float*)d_in[2];
    const float* edgef    = (const float*)d_in[3];
    const void*  idsv     =               d_in[4];
    const float* tw       = (const float*)d_in[5];
    const float* tb       = (const float*)d_in[6];
    const float* w1       = (const float*)d_in[7];
    const float* b1       = (const float*)d_in[8];
    const float* w2       = (const float*)d_in[9];
    const float* b2       = (const float*)d_in[10];
    const float* wih      = (const float*)d_in[11];
    const float* whh      = (const float*)d_in[12];
    const float* bih      = (const float*)d_in[13];
    const float* bhh      = (const float*)d_in[14];
    float* out = (float*)d_out;

    int write_ids = (out_size >= NN + NN * DM) ? 1 : 0;
    int mem_off   = write_ids ? NN : 0;

    void *p_hh; float *p_agg, *p_gih, *p_ghh, *p_tenc;
    cudaGetSymbolAddress(&p_hh, g_hh);
    cudaGetSymbolAddress((void**)&p_agg,  g_agg);
    cudaGetSymbolAddress((void**)&p_gih,  g_gih);
    cudaGetSymbolAddress((void**)&p_ghh,  g_ghh);
    cudaGetSymbolAddress((void**)&p_tenc, g_tenc);

    k_detect<<<1, 32>>>((const int*)idsv);
    k_zero<<<(NN * MSGD) / 256, 256>>>(out, write_ids);
    k_count<<<E_NUM / 256, 256>>>(idsv);
    k_scan<<<1, 1024>>>(out, write_ids);
    k_tenc<<<(E_NUM * 64) / 256, 256>>>(rel_time, tw, tb);

    // GEMM1: h = relu([src|dst|edge|t_enc] @ w1^T + b1) -> fp16   131072x512, K=704
    mma_gemm<2, 1><<<dim3(HIDN / 128, E_NUM / 128), 256>>>(
        nullptr, w1, b1, p_hh, 704, HIDN, 1, nullptr, srcm, dstm, edgef, p_tenc);

    // GEMM2: msg = h @ w2^T + b2, scatter-atomic into g_sums     131072x256, K=512
    mma_gemm<1, 2><<<dim3(MSGD / 128, E_NUM / 128), 256>>>(
        p_hh, w2, b2, nullptr, 512, MSGD, 0, idsv, nullptr, nullptr, nullptr, nullptr);

    k_agg<<<(NN * 64) / 256, 256>>>();

    // GRU: gi = agg @ wih^T + bih ; gh = prev @ whh^T + bhh       32768x768, K=256
    mma_gemm<0, 0><<<dim3((3 * DM) / 128, NN / 128), 256>>>(
        p_agg, wih, bih, p_gih, 256, 3 * DM, 0, nullptr, nullptr, nullptr, nullptr, nullptr);
    mma_gemm<0, 0><<<dim3((3 * DM) / 128, NN / 128), 256>>>(
        dstm, whh, bhh, p_ghh, 256, 3 * DM, 0, nullptr, nullptr, nullptr, nullptr, nullptr);

    k_gate<<<(NN * DM) / 256, 256>>>(dstm, out, mem_off);
}

// round 16
// speedup vs baseline: 1.8915x; 1.8786x over previous
#include <cuda_runtime.h>
#include <cuda_fp16.h>
#include <math.h>
#include <stdint.h>

#define E_NUM  131072
#define NN     32768
#define DM     256
#define HIDN   512
#define MSGD   256
#define XDIM   704

// ---------------- scratch (static device globals; no allocation) ----------
__device__ __align__(16) __half g_x16 [(size_t)E_NUM * XDIM];   // 184 MB concat input, fp16
__device__ __align__(16) __half g_hh  [(size_t)E_NUM * HIDN];   // 134 MB h, fp16
__device__ __align__(16) __half g_agg16[(size_t)NN * MSGD];     // 16.8 MB
__device__ __align__(16) __half g_dst16[(size_t)NN * DM];       // 16.8 MB
__device__ __align__(16) __half g_w1  [HIDN * XDIM];
__device__ __align__(16) __half g_w2  [MSGD * HIDN];
__device__ __align__(16) __half g_wih [3 * DM * MSGD];
__device__ __align__(16) __half g_whh [3 * DM * DM];
__device__ float g_sums[(size_t)NN * MSGD];     // 33.5 MB (indexed by id)
__device__ float g_gih [(size_t)NN * 3 * DM];   // 100 MB
__device__ float g_ghh [(size_t)NN * 3 * DM];   // 100 MB
__device__ int   g_cnt [NN];
__device__ int   g_uid [NN];
__device__ int   g_is64;

// ---------------- helpers ---------------------------------------------------
__device__ __forceinline__ uint32_t smem_u32(const void* p) {
    uint32_t a;
    asm("{ .reg .u64 t; cvta.to.shared.u64 t, %1; cvt.u32.u64 %0, t; }"
        : "=r"(a) : "l"(p));
    return a;
}
__device__ __forceinline__ void cp16(uint32_t dst, const void* src) {
    asm volatile("cp.async.ca.shared.global [%0], [%1], 16;" :: "r"(dst), "l"(src));
}
template <int N>
__device__ __forceinline__ void cp_wait() {
    asm volatile("cp.async.wait_group %0;" :: "n"(N) : "memory");
}
__device__ __forceinline__ void mma16(float* d, const uint32_t* a, const uint32_t* b) {
    asm volatile("mma.sync.aligned.m16n8k16.row.col.f32.f16.f16.f32 "
                 "{%0,%1,%2,%3}, {%4,%5,%6,%7}, {%8,%9}, {%0,%1,%2,%3};"
                 : "+f"(d[0]), "+f"(d[1]), "+f"(d[2]), "+f"(d[3])
                 : "r"(a[0]), "r"(a[1]), "r"(a[2]), "r"(a[3]),
                   "r"(b[0]), "r"(b[1]));
}
__device__ __forceinline__ void ldsm4(uint32_t* r, uint32_t addr) {
    asm volatile("ldmatrix.sync.aligned.m8n8.x4.shared.b16 {%0,%1,%2,%3}, [%4];"
                 : "=r"(r[0]), "=r"(r[1]), "=r"(r[2]), "=r"(r[3]) : "r"(addr));
}
__device__ __forceinline__ void ldsm2(uint32_t* r, uint32_t addr) {
    asm volatile("ldmatrix.sync.aligned.m8n8.x2.shared.b16 {%0,%1}, [%2];"
                 : "=r"(r[0]), "=r"(r[1]) : "r"(addr));
}

// ---------------- dtype detector for dst_ids (int32 vs int64) -------------
__global__ void k_detect(const int* ids32) {
    if (threadIdx.x == 0 && blockIdx.x == 0) {
        int z = 0;
        for (int i = 1; i < 64; i += 2) z |= ids32[i];
        g_is64 = (z == 0) ? 1 : 0;
    }
}
__device__ __forceinline__ int load_id(const void* idsv, int e) {
    if (g_is64) return (int)((const long long*)idsv)[e];
    return ((const int*)idsv)[e];
}

// ---------------- per-launch init ------------------------------------------
__global__ void k_zero(float* out, int write_ids) {
    int idx = blockIdx.x * blockDim.x + threadIdx.x;  // NN*MSGD threads
    g_sums[idx] = 0.0f;
    if (idx < NN) {
        g_cnt[idx] = 0;
        g_uid[idx] = NN;
        if (write_ids) out[idx] = (float)NN;
    }
}

// ---------------- fp32 -> fp16 convert (generic, float4 vectorized) --------
__global__ void k_cvt(__half* __restrict__ dst, const float* __restrict__ src, int n4) {
    int i = blockIdx.x * blockDim.x + threadIdx.x;
    if (i < n4) {
        float4 v = reinterpret_cast<const float4*>(src)[i];
        __half2 h0 = __floats2half2_rn(v.x, v.y);
        __half2 h1 = __floats2half2_rn(v.z, v.w);
        uint2 u; u.x = *(uint32_t*)&h0; u.y = *(uint32_t*)&h1;
        reinterpret_cast<uint2*>(dst)[i] = u;
    }
}

// ---------------- build concat fp16 matrix [src|dst|edge|cos] ---------------
__global__ void k_build_x(const float* __restrict__ srcm, const float* __restrict__ dstm,
                          const float* __restrict__ edgef, const float* __restrict__ rt,
                          const float* __restrict__ tw, const float* __restrict__ tb) {
    int idx = blockIdx.x * blockDim.x + threadIdx.x;   // E * 176 threads (4 cols each)
    int e = idx / 176;
    int c4 = (idx - e * 176) << 2;
    float4 v;
    if (c4 < 256)      v = *reinterpret_cast<const float4*>(srcm + (size_t)e * 256 + c4);
    else if (c4 < 512) v = *reinterpret_cast<const float4*>(dstm + (size_t)e * 256 + (c4 - 256));
    else if (c4 < 640) v = *reinterpret_cast<const float4*>(edgef + (size_t)e * 128 + (c4 - 512));
    else {
        float r = rt[e];
        int j = c4 - 640;
        v.x = cosf(fmaf(r, tw[j + 0], tb[j + 0]));
        v.y = cosf(fmaf(r, tw[j + 1], tb[j + 1]));
        v.z = cosf(fmaf(r, tw[j + 2], tb[j + 2]));
        v.w = cosf(fmaf(r, tw[j + 3], tb[j + 3]));
    }
    __half2 h0 = __floats2half2_rn(v.x, v.y);
    __half2 h1 = __floats2half2_rn(v.z, v.w);
    uint2 u; u.x = *(uint32_t*)&h0; u.y = *(uint32_t*)&h1;
    *reinterpret_cast<uint2*>(g_x16 + (size_t)e * XDIM + c4) = u;
}

// ---------------- per-id counts --------------------------------------------
__global__ void k_count(const void* idsv) {
    int e = blockIdx.x * blockDim.x + threadIdx.x;
    if (e < E_NUM) atomicAdd(&g_cnt[load_id(idsv, e)], 1);
}

// ---------------- sorted-unique (ballot-based, coalesced) -------------------
__global__ void k_scan(float* out, int write_ids) {
    __shared__ uint32_t masks[32][32];
    __shared__ int wtot[32];
    int lane = threadIdx.x & 31, wid = threadIdx.x >> 5;
    int tot = 0;
#pragma unroll
    for (int i = 0; i < 32; i++) {
        int id = wid * 1024 + i * 32 + lane;
        uint32_t m = __ballot_sync(0xFFFFFFFFu, g_cnt[id] > 0);
        masks[wid][i] = m;
        tot += __popc(m);
    }
    if (lane == 0) wtot[wid] = tot;
    __syncthreads();
    if (wid == 0) {
        int w = wtot[lane], v = w;
#pragma unroll
        for (int off = 1; off < 32; off <<= 1) {
            int t = __shfl_up_sync(0xFFFFFFFFu, v, off);
            if (lane >= off) v += t;
        }
        wtot[lane] = v - w;   // exclusive
    }
    __syncthreads();
    int r = wtot[wid];
#pragma unroll
    for (int i = 0; i < 32; i++) {
        uint32_t m = masks[wid][i];
        int id = wid * 1024 + i * 32 + lane;
        if (m & (1u << lane)) {
            int rk = r + __popc(m & ((1u << lane) - 1u));
            g_uid[rk] = id;
            if (write_ids) out[rk] = (float)id;
        }
        r += __popc(m);
    }
}

// ---------------- agg = sums/count in unique-slot order (fp16 out) ----------
__global__ void k_agg() {
    int idx = blockIdx.x * blockDim.x + threadIdx.x;  // NN*64
    int u = idx >> 6;
    int c4 = (idx & 63) << 2;
    int id = g_uid[u];
    float4 o = make_float4(0.f, 0.f, 0.f, 0.f);
    if (id < NN) {
        float cnt = (float)g_cnt[id];
        float4 s = *reinterpret_cast<const float4*>(g_sums + (size_t)id * MSGD + c4);
        o.x = s.x / cnt; o.y = s.y / cnt; o.z = s.z / cnt; o.w = s.w / cnt;
    }
    __half2 h0 = __floats2half2_rn(o.x, o.y);
    __half2 h1 = __floats2half2_rn(o.z, o.w);
    uint2 v; v.x = *(uint32_t*)&h0; v.y = *(uint32_t*)&h1;
    *reinterpret_cast<uint2*>(g_agg16 + (size_t)u * MSGD + c4) = v;
}

// ---------------- fp16 mma.sync GEMM: C = A(MxK) * B(NxK)^T + bias ----------
// CTA 128x128, 8 warps (2x4), warp tile 64x32 of m16n8k16. KCH=32, cp.async
// double-buffered (R8 pipeline). Smem rows padded to 40 halves (80B stride).
// OMODE: 0 = f32 store, 1 = half store, 2 = scatter-atomic into g_sums.
#define KCH   32
#define ROWH  40
#define TILE_HALFS (128 * ROWH)                  // 5120
#define STAGE_HALFS (2 * TILE_HALFS)             // A + B
#define SMEM_HALFS  (2 * STAGE_HALFS)            // 2 stages = 40960 B

template <int OMODE>
__global__ void __launch_bounds__(256, 2)
mma_gemm(const __half* __restrict__ A, const __half* __restrict__ Bw,
         const float* __restrict__ bias, void* __restrict__ Cv,
         int K, int Nld, int relu, const void* __restrict__ idsv)
{
    __shared__ __half sm[SMEM_HALFS];
    const int tid  = threadIdx.x;
    const int lane = tid & 31;
    const int wid  = tid >> 5;
    const int wm   = wid >> 2;      // 0..1  (64-row slabs)
    const int wn   = wid & 3;       // 0..3  (32-col slabs)
    const int rowBase = blockIdx.y * 128;
    const int colBase = blockIdx.x * 128;
    const uint32_t sb = smem_u32(sm);

    float acc[4][4][4];
#pragma unroll
    for (int mt = 0; mt < 4; mt++)
#pragma unroll
        for (int nt = 0; nt < 4; nt++)
#pragma unroll
            for (int r = 0; r < 4; r++) acc[mt][nt][r] = 0.0f;

    const int Cn = K / KCH;

    // ---- cp.async loader: chunk c into stage st (A: 512 cp16, B: 512 cp16)
    auto load_chunk = [&](int c, int st) {
        int k0 = c * KCH;
        uint32_t Ab = sb + (uint32_t)st * STAGE_HALFS * 2;
        uint32_t Bb = Ab + TILE_HALFS * 2;
        const __half* as = A + (size_t)rowBase * K + k0;
        const __half* bs = Bw + (size_t)colBase * K + k0;
#pragma unroll
        for (int i = 0; i < 2; ++i) {
            int idx = tid + (i << 8);
            int row = idx >> 2, seg = idx & 3;
            cp16(Ab + (uint32_t)(row * ROWH + seg * 8) * 2,
                 as + (size_t)row * K + seg * 8);
        }
#pragma unroll
        for (int i = 0; i < 2; ++i) {
            int idx = tid + (i << 8);
            int row = idx >> 2, seg = idx & 3;
            cp16(Bb + (uint32_t)(row * ROWH + seg * 8) * 2,
                 bs + (size_t)row * K + seg * 8);
        }
        asm volatile("cp.async.commit_group;" ::: "memory");
    };

    load_chunk(0, 0);
    for (int c = 0; c < Cn; ++c) {
        if (c + 1 < Cn) {
            load_chunk(c + 1, (c + 1) & 1);
            cp_wait<1>();
        } else {
            cp_wait<0>();
        }
        __syncthreads();

        const uint32_t Ab = sb + (uint32_t)(c & 1) * STAGE_HALFS * 2;
        const uint32_t Bb = Ab + TILE_HALFS * 2;

        // fragment lane mapping (validated in R15):
        const int arw = lane & 15;            // A row within 16
        const int acl = (lane >> 4) * 8;      // A col half (0/8)
        const int brw = lane & 7;             // B row within 8
        const int bcl = ((lane >> 3) & 1) * 8;

#pragma unroll
        for (int ks = 0; ks < 2; ++ks) {
            const int kb = ks * 16;
            uint32_t af[4][4], bf[4][2];
#pragma unroll
            for (int mt = 0; mt < 4; mt++) {
                int r0 = wm * 64 + mt * 16;
                ldsm4(af[mt], Ab + (uint32_t)((r0 + arw) * ROWH + kb + acl) * 2);
            }
#pragma unroll
            for (int nt = 0; nt < 4; nt++) {
                int n0 = wn * 32 + nt * 8;
                ldsm2(bf[nt], Bb + (uint32_t)((n0 + brw) * ROWH + kb + bcl) * 2);
            }
#pragma unroll
            for (int mt = 0; mt < 4; mt++)
#pragma unroll
                for (int nt = 0; nt < 4; nt++)
                    mma16(acc[mt][nt], af[mt], bf[nt]);
        }
        __syncthreads();
    }

    // ---- epilogue
#pragma unroll
    for (int mt = 0; mt < 4; mt++) {
        int r0 = rowBase + wm * 64 + mt * 16 + (lane >> 2);
        int id0 = 0, id1 = 0;
        if (OMODE == 2) { id0 = load_id(idsv, r0); id1 = load_id(idsv, r0 + 8); }
#pragma unroll
        for (int nt = 0; nt < 4; nt++) {
            int c0 = colBase + wn * 32 + nt * 8 + (lane & 3) * 2;
            float bv0 = bias[c0], bv1 = bias[c0 + 1];
            float o00 = acc[mt][nt][0] + bv0, o01 = acc[mt][nt][1] + bv1;
            float o10 = acc[mt][nt][2] + bv0, o11 = acc[mt][nt][3] + bv1;
            if (relu) {
                o00 = fmaxf(o00, 0.f); o01 = fmaxf(o01, 0.f);
                o10 = fmaxf(o10, 0.f); o11 = fmaxf(o11, 0.f);
            }
            if (OMODE == 0) {
                float* Co = (float*)Cv;
                *reinterpret_cast<float2*>(Co + (size_t)r0 * Nld + c0) = make_float2(o00, o01);
                *reinterpret_cast<float2*>(Co + (size_t)(r0 + 8) * Nld + c0) = make_float2(o10, o11);
            } else if (OMODE == 1) {
                __half* Ch = (__half*)Cv;
                *reinterpret_cast<__half2*>(Ch + (size_t)r0 * Nld + c0) = __floats2half2_rn(o00, o01);
                *reinterpret_cast<__half2*>(Ch + (size_t)(r0 + 8) * Nld + c0) = __floats2half2_rn(o10, o11);
            } else {
                atomicAdd(&g_sums[(size_t)id0 * MSGD + c0],     o00);
                atomicAdd(&g_sums[(size_t)id0 * MSGD + c0 + 1], o01);
                atomicAdd(&g_sums[(size_t)id1 * MSGD + c0],     o10);
                atomicAdd(&g_sums[(size_t)id1 * MSGD + c0 + 1], o11);
            }
        }
    }
}

// ---------------- GRU gates + output ----------------------------------------
__global__ void k_gate(const float* __restrict__ dstm, float* __restrict__ out,
                       int mem_off) {
    int idx = blockIdx.x * blockDim.x + threadIdx.x;  // NN*DM
    int u = idx >> 8;
    int c = idx & 255;
    const float* gi = g_gih + (size_t)u * (3 * DM);
    const float* gh = g_ghh + (size_t)u * (3 * DM);
    float r = 1.0f / (1.0f + expf(-(gi[c] + gh[c])));
    float z = 1.0f / (1.0f + expf(-(gi[256 + c] + gh[256 + c])));
    float n = tanhf(gi[512 + c] + r * gh[512 + c]);
    float prev = dstm[idx];
    out[mem_off + idx] = (1.0f - z) * n + z * prev;
}

// ---------------- launch -----------------------------------------------------
extern "C" void kernel_launch(void* const* d_in, const int* in_sizes, int n_in,
                              void* d_out, int out_size)
{
    const float* rel_time = (const float*)d_in[0];
    const float* srcm     = (const float*)d_in[1];
    const float* dstm     = (const float*)d_in[2];
    const float* edgef    = (const float*)d_in[3];
    const void*  idsv     =               d_in[4];
    const float* tw       = (const float*)d_in[5];
    const float* tb       = (const float*)d_in[6];
    const float* w1       = (const float*)d_in[7];
    const float* b1       = (const float*)d_in[8];
    const float* w2       = (const float*)d_in[9];
    const float* b2       = (const float*)d_in[10];
    const float* wih      = (const float*)d_in[11];
    const float* whh      = (const float*)d_in[12];
    const float* bih      = (const float*)d_in[13];
    const float* bhh      = (const float*)d_in[14];
    float* out = (float*)d_out;

    int write_ids = (out_size >= NN + NN * DM) ? 1 : 0;
    int mem_off   = write_ids ? NN : 0;

    __half *p_x16, *p_hh, *p_agg16, *p_dst16, *p_w1, *p_w2, *p_wih, *p_whh;
    float *p_gih, *p_ghh;
    cudaGetSymbolAddress((void**)&p_x16,   g_x16);
    cudaGetSymbolAddress((void**)&p_hh,    g_hh);
    cudaGetSymbolAddress((void**)&p_agg16, g_agg16);
    cudaGetSymbolAddress((void**)&p_dst16, g_dst16);
    cudaGetSymbolAddress((void**)&p_w1,    g_w1);
    cudaGetSymbolAddress((void**)&p_w2,    g_w2);
    cudaGetSymbolAddress((void**)&p_wih,   g_wih);
    cudaGetSymbolAddress((void**)&p_whh,   g_whh);
    cudaGetSymbolAddress((void**)&p_gih,   g_gih);
    cudaGetSymbolAddress((void**)&p_ghh,   g_ghh);

    k_detect<<<1, 32>>>((const int*)idsv);
    k_zero<<<(NN * MSGD) / 256, 256>>>(out, write_ids);
    k_count<<<E_NUM / 256, 256>>>(idsv);
    k_scan<<<1, 1024>>>(out, write_ids);

    // fp16 pre-conversion
    k_build_x<<<(E_NUM * 176) / 256, 256>>>(srcm, dstm, edgef, rel_time, tw, tb);
    k_cvt<<<(HIDN * XDIM / 4 + 255) / 256, 256>>>(p_w1, w1, HIDN * XDIM / 4);
    k_cvt<<<(MSGD * HIDN / 4 + 255) / 256, 256>>>(p_w2, w2, MSGD * HIDN / 4);
    k_cvt<<<(3 * DM * MSGD / 4 + 255) / 256, 256>>>(p_wih, wih, 3 * DM * MSGD / 4);
    k_cvt<<<(3 * DM * DM / 4 + 255) / 256, 256>>>(p_whh, whh, 3 * DM * DM / 4);
    k_cvt<<<(NN * DM / 4 + 255) / 256, 256>>>(p_dst16, dstm, NN * DM / 4);

    // GEMM1: h = relu(x @ w1^T + b1) -> fp16                131072x512, K=704
    mma_gemm<1><<<dim3(HIDN / 128, E_NUM / 128), 256>>>(
        p_x16, p_w1, b1, p_hh, XDIM, HIDN, 1, nullptr);

    // GEMM2: msg = h @ w2^T + b2, scatter-atomic into g_sums  131072x256, K=512
    mma_gemm<2><<<dim3(MSGD / 128, E_NUM / 128), 256>>>(
        p_hh, p_w2, b2, nullptr, HIDN, MSGD, 0, idsv);

    k_agg<<<(NN * 64) / 256, 256>>>();

    // GRU: gi = agg @ wih^T + bih ; gh = prev @ whh^T + bhh    32768x768, K=256
    mma_gemm<0><<<dim3((3 * DM) / 128, NN / 128), 256>>>(
        p_agg16, p_wih, bih, p_gih, MSGD, 3 * DM, 0, nullptr);
    mma_gemm<0><<<dim3((3 * DM) / 128, NN / 128), 256>>>(
        p_dst16, p_whh, bhh, p_ghh, DM, 3 * DM, 0, nullptr);

    k_gate<<<(NN * DM) / 256, 256>>>(dstm, out, mem_off);
}

// round 17
// speedup vs baseline: 1.8919x; 1.0002x over previous
#include <cuda_runtime.h>
#include <cuda_fp16.h>
#include <math.h>
#include <stdint.h>

#define E_NUM  131072
#define NN     32768
#define DM     256
#define HIDN   512
#define MSGD   256
#define XDIM   704

// ---------------- scratch (static device globals; no allocation) ----------
__device__ __align__(16) __half g_x16 [(size_t)E_NUM * XDIM];   // 184 MB concat input, fp16
__device__ __align__(16) __half g_hh  [(size_t)E_NUM * HIDN];   // 134 MB h, fp16
__device__ __align__(16) __half g_agg16[(size_t)NN * MSGD];     // 16.8 MB
__device__ __align__(16) __half g_dst16[(size_t)NN * DM];       // 16.8 MB
__device__ __align__(16) __half g_w1  [HIDN * XDIM];
__device__ __align__(16) __half g_w2  [MSGD * HIDN];
__device__ __align__(16) __half g_wih [3 * DM * MSGD];
__device__ __align__(16) __half g_whh [3 * DM * DM];
__device__ float g_sums[(size_t)NN * MSGD];     // 33.5 MB (indexed by id)
__device__ float g_gih [(size_t)NN * 3 * DM];   // 100 MB
__device__ float g_ghh [(size_t)NN * 3 * DM];   // 100 MB
__device__ int   g_cnt [NN];
__device__ int   g_uid [NN];
__device__ int   g_is64;

// ---------------- helpers ---------------------------------------------------
__device__ __forceinline__ uint32_t smem_u32(const void* p) {
    uint32_t a;
    asm("{ .reg .u64 t; cvta.to.shared.u64 t, %1; cvt.u32.u64 %0, t; }"
        : "=r"(a) : "l"(p));
    return a;
}
__device__ __forceinline__ void cp16(uint32_t dst, const void* src) {
    asm volatile("cp.async.ca.shared.global [%0], [%1], 16;" :: "r"(dst), "l"(src));
}
template <int N>
__device__ __forceinline__ void cp_wait() {
    asm volatile("cp.async.wait_group %0;" :: "n"(N) : "memory");
}
__device__ __forceinline__ void mma16(float* d, const uint32_t* a, const uint32_t* b) {
    asm volatile("mma.sync.aligned.m16n8k16.row.col.f32.f16.f16.f32 "
                 "{%0,%1,%2,%3}, {%4,%5,%6,%7}, {%8,%9}, {%0,%1,%2,%3};"
                 : "+f"(d[0]), "+f"(d[1]), "+f"(d[2]), "+f"(d[3])
                 : "r"(a[0]), "r"(a[1]), "r"(a[2]), "r"(a[3]),
                   "r"(b[0]), "r"(b[1]));
}
__device__ __forceinline__ void ldsm4(uint32_t* r, uint32_t addr) {
    asm volatile("ldmatrix.sync.aligned.m8n8.x4.shared.b16 {%0,%1,%2,%3}, [%4];"
                 : "=r"(r[0]), "=r"(r[1]), "=r"(r[2]), "=r"(r[3]) : "r"(addr));
}
__device__ __forceinline__ void ldsm2(uint32_t* r, uint32_t addr) {
    asm volatile("ldmatrix.sync.aligned.m8n8.x2.shared.b16 {%0,%1}, [%2];"
                 : "=r"(r[0]), "=r"(r[1]) : "r"(addr));
}

// ---------------- dtype detector for dst_ids (int32 vs int64) -------------
__global__ void k_detect(const int* ids32) {
    if (threadIdx.x == 0 && blockIdx.x == 0) {
        int z = 0;
        for (int i = 1; i < 64; i += 2) z |= ids32[i];
        g_is64 = (z == 0) ? 1 : 0;
    }
}
__device__ __forceinline__ int load_id(const void* idsv, int e) {
    if (g_is64) return (int)((const long long*)idsv)[e];
    return ((const int*)idsv)[e];
}

// ---------------- per-launch init ------------------------------------------
__global__ void k_zero(float* out, int write_ids) {
    int idx = blockIdx.x * blockDim.x + threadIdx.x;  // NN*MSGD threads
    g_sums[idx] = 0.0f;
    if (idx < NN) {
        g_cnt[idx] = 0;
        g_uid[idx] = NN;
        if (write_ids) out[idx] = (float)NN;
    }
}

// ---------------- fp32 -> fp16 convert (generic, float4 vectorized) --------
__global__ void k_cvt(__half* __restrict__ dst, const float* __restrict__ src, int n4) {
    int i = blockIdx.x * blockDim.x + threadIdx.x;
    if (i < n4) {
        float4 v = reinterpret_cast<const float4*>(src)[i];
        __half2 h0 = __floats2half2_rn(v.x, v.y);
        __half2 h1 = __floats2half2_rn(v.z, v.w);
        uint2 u; u.x = *(uint32_t*)&h0; u.y = *(uint32_t*)&h1;
        reinterpret_cast<uint2*>(dst)[i] = u;
    }
}

// ---------------- build concat fp16 matrix [src|dst|edge|cos] ---------------
__global__ void k_build_x(const float* __restrict__ srcm, const float* __restrict__ dstm,
                          const float* __restrict__ edgef, const float* __restrict__ rt,
                          const float* __restrict__ tw, const float* __restrict__ tb) {
    int idx = blockIdx.x * blockDim.x + threadIdx.x;   // E * 176 threads (4 cols each)
    int e = idx / 176;
    int c4 = (idx - e * 176) << 2;
    float4 v;
    if (c4 < 256)      v = *reinterpret_cast<const float4*>(srcm + (size_t)e * 256 + c4);
    else if (c4 < 512) v = *reinterpret_cast<const float4*>(dstm + (size_t)e * 256 + (c4 - 256));
    else if (c4 < 640) v = *reinterpret_cast<const float4*>(edgef + (size_t)e * 128 + (c4 - 512));
    else {
        float r = rt[e];
        int j = c4 - 640;
        v.x = cosf(fmaf(r, tw[j + 0], tb[j + 0]));
        v.y = cosf(fmaf(r, tw[j + 1], tb[j + 1]));
        v.z = cosf(fmaf(r, tw[j + 2], tb[j + 2]));
        v.w = cosf(fmaf(r, tw[j + 3], tb[j + 3]));
    }
    __half2 h0 = __floats2half2_rn(v.x, v.y);
    __half2 h1 = __floats2half2_rn(v.z, v.w);
    uint2 u; u.x = *(uint32_t*)&h0; u.y = *(uint32_t*)&h1;
    *reinterpret_cast<uint2*>(g_x16 + (size_t)e * XDIM + c4) = u;
}

// ---------------- per-id counts --------------------------------------------
__global__ void k_count(const void* idsv) {
    int e = blockIdx.x * blockDim.x + threadIdx.x;
    if (e < E_NUM) atomicAdd(&g_cnt[load_id(idsv, e)], 1);
}

// ---------------- sorted-unique (ballot-based, coalesced) -------------------
__global__ void k_scan(float* out, int write_ids) {
    __shared__ uint32_t masks[32][32];
    __shared__ int wtot[32];
    int lane = threadIdx.x & 31, wid = threadIdx.x >> 5;
    int tot = 0;
#pragma unroll
    for (int i = 0; i < 32; i++) {
        int id = wid * 1024 + i * 32 + lane;
        uint32_t m = __ballot_sync(0xFFFFFFFFu, g_cnt[id] > 0);
        masks[wid][i] = m;
        tot += __popc(m);
    }
    if (lane == 0) wtot[wid] = tot;
    __syncthreads();
    if (wid == 0) {
        int w = wtot[lane], v = w;
#pragma unroll
        for (int off = 1; off < 32; off <<= 1) {
            int t = __shfl_up_sync(0xFFFFFFFFu, v, off);
            if (lane >= off) v += t;
        }
        wtot[lane] = v - w;   // exclusive
    }
    __syncthreads();
    int r = wtot[wid];
#pragma unroll
    for (int i = 0; i < 32; i++) {
        uint32_t m = masks[wid][i];
        int id = wid * 1024 + i * 32 + lane;
        if (m & (1u << lane)) {
            int rk = r + __popc(m & ((1u << lane) - 1u));
            g_uid[rk] = id;
            if (write_ids) out[rk] = (float)id;
        }
        r += __popc(m);
    }
}

// ---------------- agg = sums/count in unique-slot order (fp16 out) ----------
__global__ void k_agg() {
    int idx = blockIdx.x * blockDim.x + threadIdx.x;  // NN*64
    int u = idx >> 6;
    int c4 = (idx & 63) << 2;
    int id = g_uid[u];
    float4 o = make_float4(0.f, 0.f, 0.f, 0.f);
    if (id < NN) {
        float cnt = (float)g_cnt[id];
        float4 s = *reinterpret_cast<const float4*>(g_sums + (size_t)id * MSGD + c4);
        o.x = s.x / cnt; o.y = s.y / cnt; o.z = s.z / cnt; o.w = s.w / cnt;
    }
    __half2 h0 = __floats2half2_rn(o.x, o.y);
    __half2 h1 = __floats2half2_rn(o.z, o.w);
    uint2 v; v.x = *(uint32_t*)&h0; v.y = *(uint32_t*)&h1;
    *reinterpret_cast<uint2*>(g_agg16 + (size_t)u * MSGD + c4) = v;
}

// ---------------- fp16 mma.sync GEMM: C = A(MxK) * B(NxK)^T + bias ----------
// CTA 128x128, 8 warps (2x4), warp tile 64x32 of m16n8k16. KCH=32, cp.async
// double-buffered (R8 pipeline). Smem rows padded to 40 halves (80B stride).
// OMODE: 0 = f32 store, 1 = half store, 2 = scatter-atomic into g_sums.
#define KCH   32
#define ROWH  40
#define TILE_HALFS (128 * ROWH)                  // 5120
#define STAGE_HALFS (2 * TILE_HALFS)             // A + B
#define SMEM_HALFS  (2 * STAGE_HALFS)            // 2 stages = 40960 B

template <int OMODE>
__global__ void __launch_bounds__(256, 2)
mma_gemm(const __half* __restrict__ A, const __half* __restrict__ Bw,
         const float* __restrict__ bias, void* __restrict__ Cv,
         int K, int Nld, int relu, const void* __restrict__ idsv)
{
    __shared__ __half sm[SMEM_HALFS];
    const int tid  = threadIdx.x;
    const int lane = tid & 31;
    const int wid  = tid >> 5;
    const int wm   = wid >> 2;      // 0..1  (64-row slabs)
    const int wn   = wid & 3;       // 0..3  (32-col slabs)
    const int rowBase = blockIdx.y * 128;
    const int colBase = blockIdx.x * 128;
    const uint32_t sb = smem_u32(sm);

    float acc[4][4][4];
#pragma unroll
    for (int mt = 0; mt < 4; mt++)
#pragma unroll
        for (int nt = 0; nt < 4; nt++)
#pragma unroll
            for (int r = 0; r < 4; r++) acc[mt][nt][r] = 0.0f;

    const int Cn = K / KCH;

    // ---- cp.async loader: chunk c into stage st (A: 512 cp16, B: 512 cp16)
    auto load_chunk = [&](int c, int st) {
        int k0 = c * KCH;
        uint32_t Ab = sb + (uint32_t)st * STAGE_HALFS * 2;
        uint32_t Bb = Ab + TILE_HALFS * 2;
        const __half* as = A + (size_t)rowBase * K + k0;
        const __half* bs = Bw + (size_t)colBase * K + k0;
#pragma unroll
        for (int i = 0; i < 2; ++i) {
            int idx = tid + (i << 8);
            int row = idx >> 2, seg = idx & 3;
            cp16(Ab + (uint32_t)(row * ROWH + seg * 8) * 2,
                 as + (size_t)row * K + seg * 8);
        }
#pragma unroll
        for (int i = 0; i < 2; ++i) {
            int idx = tid + (i << 8);
            int row = idx >> 2, seg = idx & 3;
            cp16(Bb + (uint32_t)(row * ROWH + seg * 8) * 2,
                 bs + (size_t)row * K + seg * 8);
        }
        asm volatile("cp.async.commit_group;" ::: "memory");
    };

    load_chunk(0, 0);
    for (int c = 0; c < Cn; ++c) {
        if (c + 1 < Cn) {
            load_chunk(c + 1, (c + 1) & 1);
            cp_wait<1>();
        } else {
            cp_wait<0>();
        }
        __syncthreads();

        const uint32_t Ab = sb + (uint32_t)(c & 1) * STAGE_HALFS * 2;
        const uint32_t Bb = Ab + TILE_HALFS * 2;

        // fragment lane mapping (validated in R15):
        const int arw = lane & 15;            // A row within 16
        const int acl = (lane >> 4) * 8;      // A col half (0/8)
        const int brw = lane & 7;             // B row within 8
        const int bcl = ((lane >> 3) & 1) * 8;

#pragma unroll
        for (int ks = 0; ks < 2; ++ks) {
            const int kb = ks * 16;
            uint32_t af[4][4], bf[4][2];
#pragma unroll
            for (int mt = 0; mt < 4; mt++) {
                int r0 = wm * 64 + mt * 16;
                ldsm4(af[mt], Ab + (uint32_t)((r0 + arw) * ROWH + kb + acl) * 2);
            }
#pragma unroll
            for (int nt = 0; nt < 4; nt++) {
                int n0 = wn * 32 + nt * 8;
                ldsm2(bf[nt], Bb + (uint32_t)((n0 + brw) * ROWH + kb + bcl) * 2);
            }
#pragma unroll
            for (int mt = 0; mt < 4; mt++)
#pragma unroll
                for (int nt = 0; nt < 4; nt++)
                    mma16(acc[mt][nt], af[mt], bf[nt]);
        }
        __syncthreads();
    }

    // ---- epilogue
#pragma unroll
    for (int mt = 0; mt < 4; mt++) {
        int r0 = rowBase + wm * 64 + mt * 16 + (lane >> 2);
        int id0 = 0, id1 = 0;
        if (OMODE == 2) { id0 = load_id(idsv, r0); id1 = load_id(idsv, r0 + 8); }
#pragma unroll
        for (int nt = 0; nt < 4; nt++) {
            int c0 = colBase + wn * 32 + nt * 8 + (lane & 3) * 2;
            float bv0 = bias[c0], bv1 = bias[c0 + 1];
            float o00 = acc[mt][nt][0] + bv0, o01 = acc[mt][nt][1] + bv1;
            float o10 = acc[mt][nt][2] + bv0, o11 = acc[mt][nt][3] + bv1;
            if (relu) {
                o00 = fmaxf(o00, 0.f); o01 = fmaxf(o01, 0.f);
                o10 = fmaxf(o10, 0.f); o11 = fmaxf(o11, 0.f);
            }
            if (OMODE == 0) {
                float* Co = (float*)Cv;
                *reinterpret_cast<float2*>(Co + (size_t)r0 * Nld + c0) = make_float2(o00, o01);
                *reinterpret_cast<float2*>(Co + (size_t)(r0 + 8) * Nld + c0) = make_float2(o10, o11);
            } else if (OMODE == 1) {
                __half* Ch = (__half*)Cv;
                *reinterpret_cast<__half2*>(Ch + (size_t)r0 * Nld + c0) = __floats2half2_rn(o00, o01);
                *reinterpret_cast<__half2*>(Ch + (size_t)(r0 + 8) * Nld + c0) = __floats2half2_rn(o10, o11);
            } else {
                atomicAdd(&g_sums[(size_t)id0 * MSGD + c0],     o00);
                atomicAdd(&g_sums[(size_t)id0 * MSGD + c0 + 1], o01);
                atomicAdd(&g_sums[(size_t)id1 * MSGD + c0],     o10);
                atomicAdd(&g_sums[(size_t)id1 * MSGD + c0 + 1], o11);
            }
        }
    }
}

// ---------------- GRU gates + output ----------------------------------------
__global__ void k_gate(const float* __restrict__ dstm, float* __restrict__ out,
                       int mem_off) {
    int idx = blockIdx.x * blockDim.x + threadIdx.x;  // NN*DM
    int u = idx >> 8;
    int c = idx & 255;
    const float* gi = g_gih + (size_t)u * (3 * DM);
    const float* gh = g_ghh + (size_t)u * (3 * DM);
    float r = 1.0f / (1.0f + expf(-(gi[c] + gh[c])));
    float z = 1.0f / (1.0f + expf(-(gi[256 + c] + gh[256 + c])));
    float n = tanhf(gi[512 + c] + r * gh[512 + c]);
    float prev = dstm[idx];
    out[mem_off + idx] = (1.0f - z) * n + z * prev;
}

// ---------------- launch -----------------------------------------------------
extern "C" void kernel_launch(void* const* d_in, const int* in_sizes, int n_in,
                              void* d_out, int out_size)
{
    const float* rel_time = (const float*)d_in[0];
    const float* srcm     = (const float*)d_in[1];
    const float* dstm     = (const float*)d_in[2];
    const float* edgef    = (const float*)d_in[3];
    const void*  idsv     =               d_in[4];
    const float* tw       = (const float*)d_in[5];
    const float* tb       = (const float*)d_in[6];
    const float* w1       = (const float*)d_in[7];
    const float* b1       = (const float*)d_in[8];
    const float* w2       = (const float*)d_in[9];
    const float* b2       = (const float*)d_in[10];
    const float* wih      = (const float*)d_in[11];
    const float* whh      = (const float*)d_in[12];
    const float* bih      = (const float*)d_in[13];
    const float* bhh      = (const float*)d_in[14];
    float* out = (float*)d_out;

    int write_ids = (out_size >= NN + NN * DM) ? 1 : 0;
    int mem_off   = write_ids ? NN : 0;

    __half *p_x16, *p_hh, *p_agg16, *p_dst16, *p_w1, *p_w2, *p_wih, *p_whh;
    float *p_gih, *p_ghh;
    cudaGetSymbolAddress((void**)&p_x16,   g_x16);
    cudaGetSymbolAddress((void**)&p_hh,    g_hh);
    cudaGetSymbolAddress((void**)&p_agg16, g_agg16);
    cudaGetSymbolAddress((void**)&p_dst16, g_dst16);
    cudaGetSymbolAddress((void**)&p_w1,    g_w1);
    cudaGetSymbolAddress((void**)&p_w2,    g_w2);
    cudaGetSymbolAddress((void**)&p_wih,   g_wih);
    cudaGetSymbolAddress((void**)&p_whh,   g_whh);
    cudaGetSymbolAddress((void**)&p_gih,   g_gih);
    cudaGetSymbolAddress((void**)&p_ghh,   g_ghh);

    k_detect<<<1, 32>>>((const int*)idsv);
    k_zero<<<(NN * MSGD) / 256, 256>>>(out, write_ids);
    k_count<<<E_NUM / 256, 256>>>(idsv);
    k_scan<<<1, 1024>>>(out, write_ids);

    // fp16 pre-conversion
    k_build_x<<<(E_NUM * 176) / 256, 256>>>(srcm, dstm, edgef, rel_time, tw, tb);
    k_cvt<<<(HIDN * XDIM / 4 + 255) / 256, 256>>>(p_w1, w1, HIDN * XDIM / 4);
    k_cvt<<<(MSGD * HIDN / 4 + 255) / 256, 256>>>(p_w2, w2, MSGD * HIDN / 4);
    k_cvt<<<(3 * DM * MSGD / 4 + 255) / 256, 256>>>(p_wih, wih, 3 * DM * MSGD / 4);
    k_cvt<<<(3 * DM * DM / 4 + 255) / 256, 256>>>(p_whh, whh, 3 * DM * DM / 4);
    k_cvt<<<(NN * DM / 4 + 255) / 256, 256>>>(p_dst16, dstm, NN * DM / 4);

    // GEMM1: h = relu(x @ w1^T + b1) -> fp16                131072x512, K=704
    mma_gemm<1><<<dim3(HIDN / 128, E_NUM / 128), 256>>>(
        p_x16, p_w1, b1, p_hh, XDIM, HIDN, 1, nullptr);

    // GEMM2: msg = h @ w2^T + b2, scatter-atomic into g_sums  131072x256, K=512
    mma_gemm<2><<<dim3(MSGD / 128, E_NUM / 128), 256>>>(
        p_hh, p_w2, b2, nullptr, HIDN, MSGD, 0, idsv);

    k_agg<<<(NN * 64) / 256, 256>>>();

    // GRU: gi = agg @ wih^T + bih ; gh = prev @ whh^T + bhh    32768x768, K=256
    mma_gemm<0><<<dim3((3 * DM) / 128, NN / 128), 256>>>(
        p_agg16, p_wih, bih, p_gih, MSGD, 3 * DM, 0, nullptr);
    mma_gemm<0><<<dim3((3 * DM) / 128, NN / 128), 256>>>(
        p_dst16, p_whh, bhh, p_ghh, DM, 3 * DM, 0, nullptr);

    k_gate<<<(NN * DM) / 256, 256>>>(dstm, out, mem_off);
}